// round 1
// baseline (speedup 1.0000x reference)
#include <cuda_runtime.h>
#include <cuda_bf16.h>

#define T_N 1024
#define C_N 768
#define H_N 12
#define D_N 64
#define NT_N 8
#define LOG2E 1.4426950408889634f

// ---------------- scratch (static device globals; no allocation) ----------------
__device__ float g_qkvg[T_N * 4 * C_N];      // [T][3072]
__device__ float g_q[H_N * T_N * D_N];       // [H][T][D]
__device__ float g_k[H_N * T_N * D_N];
__device__ float g_v[H_N * T_N * D_N];
__device__ float g_g[H_N * T_N * D_N];       // rmsnormed g
__device__ float g_g2[H_N * T_N];            // ||g||^2 per (h,t)
__device__ float g_y[T_N * C_N];             // attention out, [T][C] layout

struct Consts {
    float inv4tau[H_N][NT_N];
    float wte[H_N][NT_N];     // softmax(logit_w) + 1e-12
    float neghb[H_N];         // -(clip(beta)/2)
    float dpc[H_N];           // dp_scale / (sqrt(64)*0.8)
    float lks[H_N];           // logk_scale * ln2 (log2 -> ln)
    float outs[H_N];
    float lam, oml, alpha;
};
__device__ Consts g_c;

__device__ __forceinline__ float ex2f_(float x){ float y; asm("ex2.approx.ftz.f32 %0, %1;":"=f"(y):"f"(x)); return y; }
__device__ __forceinline__ float lg2f_(float x){ float y; asm("lg2.approx.ftz.f32 %0, %1;":"=f"(y):"f"(x)); return y; }

// ---------------- constants precompute ----------------
__global__ void const_kernel(const float* lam_p, const float* log_tau,
                             const float* logit_w, const float* beta,
                             const float* out_scale, const float* dp_scale,
                             const float* logk_scale, const float* dt_logit) {
    if (threadIdx.x != 0 || blockIdx.x != 0) return;
    for (int h = 0; h < H_N; ++h) {
        float mx = -1e30f;
        for (int t = 0; t < NT_N; ++t) mx = fmaxf(mx, logit_w[h*NT_N+t]);
        float s = 0.f, e[NT_N];
        for (int t = 0; t < NT_N; ++t) { e[t] = expf(logit_w[h*NT_N+t]-mx); s += e[t]; }
        for (int t = 0; t < NT_N; ++t) g_c.wte[h][t] = e[t]/s + 1e-12f;
        for (int t = 0; t < NT_N; ++t) {
            float tau = fmaxf(expf(log_tau[h*NT_N+t]), 1e-6f);
            g_c.inv4tau[h][t] = 1.f/(4.f*tau);
        }
        float bc = fminf(fmaxf(beta[h], 0.5f), 2.5f);
        g_c.neghb[h] = -0.5f*bc;
        g_c.dpc[h]   = dp_scale[h]/(8.0f*0.8f);
        g_c.lks[h]   = logk_scale[h]*0.6931471805599453f;
        g_c.outs[h]  = out_scale[h];
    }
    float lam = lam_p[0];
    g_c.lam = lam; g_c.oml = 1.f - lam;
    g_c.alpha = 0.1f/(1.f+expf(-dt_logit[0]));
}

// ---------------- GEMM: C[M,N] = A[M,K] * B[N,K]^T (both row-major, NT form) ----------------
__global__ __launch_bounds__(256) void gemm_nt_128(const float* __restrict__ A,
        const float* __restrict__ B, float* __restrict__ C, int M, int N, int K) {
    __shared__ float As[16][132];
    __shared__ float Bs[16][132];
    int tid = threadIdx.x;
    int m0 = blockIdx.y*128, n0 = blockIdx.x*128;
    int ty = tid >> 4, tx = tid & 15;
    int lr = tid >> 2, lc = (tid & 3)*4;
    const float* Ap = A + (size_t)(m0+lr)*K + lc;
    const float* Bp = B + (size_t)(n0+lr)*K + lc;
    float acc[8][8] = {};
    for (int k0 = 0; k0 < K; k0 += 16) {
        float4 a0 = *(const float4*)(Ap + k0);
        float4 a1 = *(const float4*)(Ap + (size_t)64*K + k0);
        float4 b0 = *(const float4*)(Bp + k0);
        float4 b1 = *(const float4*)(Bp + (size_t)64*K + k0);
        __syncthreads();
        As[lc+0][lr]=a0.x; As[lc+1][lr]=a0.y; As[lc+2][lr]=a0.z; As[lc+3][lr]=a0.w;
        As[lc+0][lr+64]=a1.x; As[lc+1][lr+64]=a1.y; As[lc+2][lr+64]=a1.z; As[lc+3][lr+64]=a1.w;
        Bs[lc+0][lr]=b0.x; Bs[lc+1][lr]=b0.y; Bs[lc+2][lr]=b0.z; Bs[lc+3][lr]=b0.w;
        Bs[lc+0][lr+64]=b1.x; Bs[lc+1][lr+64]=b1.y; Bs[lc+2][lr+64]=b1.z; Bs[lc+3][lr+64]=b1.w;
        __syncthreads();
        #pragma unroll
        for (int kk = 0; kk < 16; ++kk) {
            float4 a4 = *(const float4*)&As[kk][ty*4];
            float4 a5 = *(const float4*)&As[kk][64+ty*4];
            float4 b4 = *(const float4*)&Bs[kk][tx*4];
            float4 b5 = *(const float4*)&Bs[kk][64+tx*4];
            float av[8] = {a4.x,a4.y,a4.z,a4.w,a5.x,a5.y,a5.z,a5.w};
            float bv[8] = {b4.x,b4.y,b4.z,b4.w,b5.x,b5.y,b5.z,b5.w};
            #pragma unroll
            for (int r = 0; r < 8; ++r)
                #pragma unroll
                for (int c = 0; c < 8; ++c)
                    acc[r][c] = fmaf(av[r], bv[c], acc[r][c]);
        }
    }
    #pragma unroll
    for (int r = 0; r < 8; ++r) {
        int row = m0 + ((r < 4) ? (ty*4+r) : (64+ty*4+r-4));
        float4 c0 = {acc[r][0],acc[r][1],acc[r][2],acc[r][3]};
        float4 c1 = {acc[r][4],acc[r][5],acc[r][6],acc[r][7]};
        *(float4*)(C + (size_t)row*N + n0 + tx*4) = c0;
        *(float4*)(C + (size_t)row*N + n0 + 64 + tx*4) = c1;
    }
}

__global__ __launch_bounds__(256) void gemm_nt_64(const float* __restrict__ A,
        const float* __restrict__ B, float* __restrict__ C, int M, int N, int K) {
    __shared__ float As[16][68];
    __shared__ float Bs[16][68];
    int tid = threadIdx.x;
    int m0 = blockIdx.y*64, n0 = blockIdx.x*64;
    int ty = tid >> 4, tx = tid & 15;
    int lr = tid >> 2, lc = (tid & 3)*4;
    const float* Ap = A + (size_t)(m0+lr)*K + lc;
    const float* Bp = B + (size_t)(n0+lr)*K + lc;
    float acc[4][4] = {};
    for (int k0 = 0; k0 < K; k0 += 16) {
        float4 a0 = *(const float4*)(Ap + k0);
        float4 b0 = *(const float4*)(Bp + k0);
        __syncthreads();
        As[lc+0][lr]=a0.x; As[lc+1][lr]=a0.y; As[lc+2][lr]=a0.z; As[lc+3][lr]=a0.w;
        Bs[lc+0][lr]=b0.x; Bs[lc+1][lr]=b0.y; Bs[lc+2][lr]=b0.z; Bs[lc+3][lr]=b0.w;
        __syncthreads();
        #pragma unroll
        for (int kk = 0; kk < 16; ++kk) {
            float4 a4 = *(const float4*)&As[kk][ty*4];
            float4 b4 = *(const float4*)&Bs[kk][tx*4];
            float av[4] = {a4.x,a4.y,a4.z,a4.w};
            float bv[4] = {b4.x,b4.y,b4.z,b4.w};
            #pragma unroll
            for (int r = 0; r < 4; ++r)
                #pragma unroll
                for (int c = 0; c < 4; ++c)
                    acc[r][c] = fmaf(av[r], bv[c], acc[r][c]);
        }
    }
    #pragma unroll
    for (int r = 0; r < 4; ++r) {
        int row = m0 + ty*4 + r;
        float4 c0 = {acc[r][0],acc[r][1],acc[r][2],acc[r][3]};
        *(float4*)(C + (size_t)row*N + n0 + tx*4) = c0;
    }
}

// ---------------- reorg: split heads + rmsnorm(g) + g2 ----------------
__global__ __launch_bounds__(256) void reorg_kernel(const float* __restrict__ gnw) {
    int gw = (blockIdx.x*256 + threadIdx.x) >> 5;
    int lane = threadIdx.x & 31;
    if (gw >= T_N*H_N) return;
    int t = gw / H_N, h = gw % H_N;
    const float* row = g_qkvg + (size_t)t*(4*C_N);
    int col = h*D_N + lane*2;
    int o = (h*T_N + t)*D_N + lane*2;
    float2 qv = *(const float2*)(row + col);
    float2 kv = *(const float2*)(row + C_N + col);
    float2 vv = *(const float2*)(row + 2*C_N + col);
    float2 gv = *(const float2*)(row + 3*C_N + col);
    *(float2*)(g_q + o) = qv;
    *(float2*)(g_k + o) = kv;
    *(float2*)(g_v + o) = vv;
    float ss = gv.x*gv.x + gv.y*gv.y;
    #pragma unroll
    for (int m = 16; m; m >>= 1) ss += __shfl_xor_sync(0xffffffffu, ss, m);
    float r = rsqrtf(ss*(1.0f/D_N) + 1e-6f);
    float2 wv = *(const float2*)(gnw + lane*2);
    float g0 = gv.x*r*wv.x, g1 = gv.y*r*wv.y;
    float2 gn = {g0, g1};
    *(float2*)(g_g + o) = gn;
    float s2 = g0*g0 + g1*g1;
    #pragma unroll
    for (int m = 16; m; m >>= 1) s2 += __shfl_xor_sync(0xffffffffu, s2, m);
    if (lane == 0) g_g2[h*T_N + t] = s2;
}

// ---------------- fused flash-style attention ----------------
// y_i = out_scale * [ (1-a)*(Pv)_i + a/(1+P_ii)*((Pv)_i + P_ii*v_i) ]
#define TILE_F (64*68)
#define ATT_SMEM_BYTES ((6*TILE_F + 192)*4)

__global__ __launch_bounds__(256, 2) void attn_kernel() {
    extern __shared__ float sm[];
    float* Qs  = sm;
    float* Gis = sm + TILE_F;
    float* Ks  = sm + 2*TILE_F;
    float* Gjs = sm + 3*TILE_F;
    float* Vs  = sm + 4*TILE_F;
    float* Pt  = sm + 5*TILE_F;
    float* g2i = sm + 6*TILE_F;
    float* g2j = g2i + 64;
    float* wiis = g2j + 64;

    int bid = blockIdx.x;
    int h = bid % H_N;
    int it = 15 - bid / H_N;          // heavy i-tiles launch first
    int i0 = it * 64;
    int tid = threadIdx.x;
    int ti = tid >> 4, tj = tid & 15;

    float inv4tau[8], wte[8];
    #pragma unroll
    for (int t = 0; t < 8; ++t) { inv4tau[t] = g_c.inv4tau[h][t]; wte[t] = g_c.wte[h][t]; }
    float neghb = g_c.neghb[h], dpc = g_c.dpc[h], lks = g_c.lks[h];
    float lam = g_c.lam, oml = g_c.oml, alpha = g_c.alpha, outs = g_c.outs[h];

    // load Q & Gi tiles (d-major, transposed)
    const float* qg  = g_q + (size_t)(h*T_N + i0)*D_N;
    const float* gig = g_g + (size_t)(h*T_N + i0)*D_N;
    #pragma unroll
    for (int mm = 0; mm < 4; ++mm) {
        int e = tid + mm*256;
        int r = e >> 4, dc = (e & 15)*4;
        float4 a = *(const float4*)(qg + r*D_N + dc);
        Qs[(dc+0)*68+r]=a.x; Qs[(dc+1)*68+r]=a.y; Qs[(dc+2)*68+r]=a.z; Qs[(dc+3)*68+r]=a.w;
        float4 b = *(const float4*)(gig + r*D_N + dc);
        Gis[(dc+0)*68+r]=b.x; Gis[(dc+1)*68+r]=b.y; Gis[(dc+2)*68+r]=b.z; Gis[(dc+3)*68+r]=b.w;
    }
    if (tid < 64) g2i[tid] = g_g2[h*T_N + i0 + tid];

    float m_r[4], l_r[4], acc[4][4], wii[4];
    #pragma unroll
    for (int r = 0; r < 4; ++r) {
        m_r[r] = -1e30f; l_r[r] = 0.f; wii[r] = 0.f;
        #pragma unroll
        for (int c = 0; c < 4; ++c) acc[r][c] = 0.f;
    }

    for (int jt = 0; jt <= it; ++jt) {
        int j0 = jt*64;
        __syncthreads();
        const float* kg  = g_k + (size_t)(h*T_N + j0)*D_N;
        const float* gjg = g_g + (size_t)(h*T_N + j0)*D_N;
        const float* vg  = g_v + (size_t)(h*T_N + j0)*D_N;
        #pragma unroll
        for (int mm = 0; mm < 4; ++mm) {
            int e = tid + mm*256;
            int r = e >> 4, dc = (e & 15)*4;
            float4 a = *(const float4*)(kg + r*D_N + dc);
            Ks[(dc+0)*68+r]=a.x; Ks[(dc+1)*68+r]=a.y; Ks[(dc+2)*68+r]=a.z; Ks[(dc+3)*68+r]=a.w;
            float4 b = *(const float4*)(gjg + r*D_N + dc);
            Gjs[(dc+0)*68+r]=b.x; Gjs[(dc+1)*68+r]=b.y; Gjs[(dc+2)*68+r]=b.z; Gjs[(dc+3)*68+r]=b.w;
            float4 c4 = *(const float4*)(vg + r*D_N + dc);
            *(float4*)(Vs + r*68 + dc) = c4;
        }
        if (tid < 64) g2j[tid] = g_g2[h*T_N + j0 + tid];
        __syncthreads();

        // score mini-GEMM: dp = q.k, gg = g_i.g_j  (4x4 per thread)
        float dp[4][4] = {}, gg[4][4] = {};
        #pragma unroll 8
        for (int d = 0; d < 64; ++d) {
            float4 qa = *(const float4*)(Qs + d*68 + ti*4);
            float4 kb = *(const float4*)(Ks + d*68 + tj*4);
            float4 ga = *(const float4*)(Gis + d*68 + ti*4);
            float4 gb = *(const float4*)(Gjs + d*68 + tj*4);
            float qv4[4]={qa.x,qa.y,qa.z,qa.w}, kv4[4]={kb.x,kb.y,kb.z,kb.w};
            float gv4[4]={ga.x,ga.y,ga.z,ga.w}, hb4[4]={gb.x,gb.y,gb.z,gb.w};
            #pragma unroll
            for (int r = 0; r < 4; ++r)
                #pragma unroll
                for (int c = 0; c < 4; ++c) {
                    dp[r][c] = fmaf(qv4[r], kv4[c], dp[r][c]);
                    gg[r][c] = fmaf(gv4[r], hb4[c], gg[r][c]);
                }
        }

        // epilogue: blended score per element
        float mt[4];
        #pragma unroll
        for (int r = 0; r < 4; ++r) {
            int ig = i0 + ti*4 + r;
            float g2ir = g2i[ti*4+r];
            mt[r] = -1e30f;
            #pragma unroll
            for (int c = 0; c < 4; ++c) {
                int jg = j0 + tj*4 + c;
                float bl = -1e30f;
                if (jg <= ig) {
                    float s = fmaxf(g2ir + g2j[tj*4+c] - 2.f*gg[r][c], 0.f);
                    float Ksum = 0.f;
                    #pragma unroll
                    for (int t = 0; t < 8; ++t) {
                        float u = fmaf(s, inv4tau[t], 1.f);
                        Ksum = fmaf(wte[t], ex2f_(neghb * lg2f_(u)), Ksum);
                    }
                    float logK = lks * lg2f_(Ksum);
                    bl = fmaf(lam, dp[r][c]*dpc, oml*logK);
                }
                dp[r][c] = bl;
                mt[r] = fmaxf(mt[r], bl);
            }
        }
        // online softmax update (row reduce over 16 tj lanes)
        #pragma unroll
        for (int r = 0; r < 4; ++r) {
            #pragma unroll
            for (int o = 8; o; o >>= 1) mt[r] = fmaxf(mt[r], __shfl_xor_sync(0xffffffffu, mt[r], o));
            float mnew = fmaxf(m_r[r], mt[r]);
            float sc = ex2f_((m_r[r]-mnew)*LOG2E);
            m_r[r] = mnew;
            l_r[r] *= sc;
            #pragma unroll
            for (int c = 0; c < 4; ++c) acc[r][c] *= sc;
            float ps = 0.f;
            #pragma unroll
            for (int c = 0; c < 4; ++c) {
                float p = ex2f_((dp[r][c]-mnew)*LOG2E);
                dp[r][c] = p;
                ps += p;
            }
            #pragma unroll
            for (int o = 8; o; o >>= 1) ps += __shfl_xor_sync(0xffffffffu, ps, o);
            l_r[r] += ps;
        }
        if (jt == it && tj == ti) {
            #pragma unroll
            for (int r = 0; r < 4; ++r) wii[r] = dp[r][r];   // diag weight (final m)
        }
        // write P transposed (xor-swizzled column groups)
        #pragma unroll
        for (int c = 0; c < 4; ++c) {
            int lj = tj*4 + c;
            int sg = (ti ^ lj) & 15;
            #pragma unroll
            for (int r = 0; r < 4; ++r) Pt[lj*68 + sg*4 + r] = dp[r][c];
        }
        __syncthreads();
        // PV accumulate
        #pragma unroll 4
        for (int j = 0; j < 64; ++j) {
            int sg = (ti ^ j) & 15;
            float4 pv = *(const float4*)(Pt + j*68 + sg*4);
            float4 vv = *(const float4*)(Vs + j*68 + tj*4);
            float pa[4]={pv.x,pv.y,pv.z,pv.w}, vb[4]={vv.x,vv.y,vv.z,vv.w};
            #pragma unroll
            for (int r = 0; r < 4; ++r)
                #pragma unroll
                for (int c = 0; c < 4; ++c)
                    acc[r][c] = fmaf(pa[r], vb[c], acc[r][c]);
        }
    }

    if (tj == ti) {
        #pragma unroll
        for (int r = 0; r < 4; ++r) wiis[ti*4+r] = wii[r];
    }
    __syncthreads();

    #pragma unroll
    for (int r = 0; r < 4; ++r) {
        int ig = i0 + ti*4 + r;
        float linv = 1.f / fmaxf(l_r[r], 1e-12f);
        float pii = wiis[ti*4+r] * linv;
        float ca = 1.f - alpha;
        float cb = alpha / (1.f + pii);
        float4 vv = *(const float4*)(g_v + (size_t)(h*T_N + ig)*D_N + tj*4);
        float vb[4] = {vv.x,vv.y,vv.z,vv.w};
        float4 outv;
        float* op = (float*)&outv;
        #pragma unroll
        for (int c = 0; c < 4; ++c) {
            float pv = acc[r][c]*linv;
            op[c] = outs * (ca*pv + cb*(pv + pii*vb[c]));
        }
        *(float4*)(g_y + (size_t)ig*C_N + h*D_N + tj*4) = outv;
    }
}

// ---------------- launch ----------------
extern "C" void kernel_launch(void* const* d_in, const int* in_sizes, int n_in,
                              void* d_out, int out_size) {
    const float* x         = (const float*)d_in[0];
    const float* W_qkvg    = (const float*)d_in[1];
    const float* W_out     = (const float*)d_in[2];
    const float* lam       = (const float*)d_in[3];
    const float* log_tau   = (const float*)d_in[4];
    const float* logit_w   = (const float*)d_in[5];
    const float* beta      = (const float*)d_in[6];
    const float* out_scale = (const float*)d_in[7];
    const float* dp_scale  = (const float*)d_in[8];
    const float* logk_sc   = (const float*)d_in[9];
    const float* dt_logit  = (const float*)d_in[10];
    const float* gnw       = (const float*)d_in[11];
    float* out = (float*)d_out;

    float *qkvg_p = nullptr, *y_p = nullptr;
    cudaGetSymbolAddress((void**)&qkvg_p, g_qkvg);
    cudaGetSymbolAddress((void**)&y_p, g_y);

    cudaFuncSetAttribute(attn_kernel, cudaFuncAttributeMaxDynamicSharedMemorySize, ATT_SMEM_BYTES);

    const_kernel<<<1, 32>>>(lam, log_tau, logit_w, beta, out_scale, dp_scale, logk_sc, dt_logit);
    gemm_nt_128<<<dim3(3072/128, 1024/128), 256>>>(x, W_qkvg, qkvg_p, T_N, 4*C_N, C_N);
    reorg_kernel<<<(T_N*H_N*32)/256, 256>>>(gnw);
    attn_kernel<<<192, 256, ATT_SMEM_BYTES>>>();
    gemm_nt_64<<<dim3(768/64, 1024/64), 256>>>(y_p, W_out, out, T_N, C_N, C_N);
}

// round 2
// speedup vs baseline: 1.2868x; 1.2868x over previous
#include <cuda_runtime.h>
#include <cuda_bf16.h>

#define T_N 1024
#define C_N 768
#define H_N 12
#define D_N 64
#define NT_N 8
#define LOG2E 1.4426950408889634f

// ---------------- scratch (static device globals; no allocation) ----------------
__device__ float g_qkvg[T_N * 4 * C_N];      // [T][3072]
__device__ float g_q[H_N * T_N * D_N];       // [H][T][D]
__device__ float g_k[H_N * T_N * D_N];
__device__ float g_v[H_N * T_N * D_N];
__device__ float g_g[H_N * T_N * D_N];       // rmsnormed g
__device__ float g_g2[H_N * T_N];            // ||g||^2 per (h,t)
__device__ float g_y[T_N * C_N];             // attention out, [T][C] layout

// split-j partials: 40 units per head (chunks of <=4 j-tiles)
__device__ float g_pacc[H_N * 40 * 64 * 64]; // [h][unit][row][col]
__device__ float g_pm[H_N * 40 * 64];
__device__ float g_pl[H_N * 40 * 64];
__device__ float g_dw[H_N * 16 * 64];        // diag weights per (h,it,row)

// unit tables: heavy (4-tile) units first for scheduling
__constant__ int c_uit[40] = {15,15,15,15,14,14,14,13,13,13,12,12,12,11,11,11,10,10,9,9,8,8,7,7,6,5,4,3,
                              14,10,6,2, 13,9,5,1, 12,8,4,0};
__constant__ int c_uc[40]  = { 0, 1, 2, 3, 0, 1, 2, 0, 1, 2, 0, 1, 2, 0, 1, 2, 0, 1,0,1,0,1,0,1,0,0,0,0,
                               3, 2,1,0,  3,2,1,0,  3,2,1,0};
__constant__ int c_off[16] = {0,1,2,3,4,6,8,10,12,15,18,21,24,28,32,36};

struct Consts {
    float inv4tau[H_N][NT_N];
    float wte[H_N][NT_N];     // softmax(logit_w) + 1e-12
    float neghb[H_N];         // -(clip(beta)/2)
    float dpl[H_N];           // lam * dp_scale/(8*0.8)
    float glk[H_N];           // (1-lam) * logk_scale * ln2
    float outs[H_N];
    float fA[H_N], fB[H_N], i4t0[H_N];
    int   fastf[H_N];
    float alpha;
};
__device__ Consts g_c;

__device__ __forceinline__ float ex2f_(float x){ float y; asm("ex2.approx.ftz.f32 %0, %1;":"=f"(y):"f"(x)); return y; }
__device__ __forceinline__ float lg2f_(float x){ float y; asm("lg2.approx.ftz.f32 %0, %1;":"=f"(y):"f"(x)); return y; }

// ---------------- constants precompute ----------------
__global__ void const_kernel(const float* lam_p, const float* log_tau,
                             const float* logit_w, const float* beta,
                             const float* out_scale, const float* dp_scale,
                             const float* logk_scale, const float* dt_logit) {
    if (threadIdx.x != 0 || blockIdx.x != 0) return;
    float lam = lam_p[0];
    for (int h = 0; h < H_N; ++h) {
        float mx = -1e30f;
        for (int t = 0; t < NT_N; ++t) mx = fmaxf(mx, logit_w[h*NT_N+t]);
        float s = 0.f, e[NT_N];
        for (int t = 0; t < NT_N; ++t) { e[t] = expf(logit_w[h*NT_N+t]-mx); s += e[t]; }
        float W = 0.f;
        for (int t = 0; t < NT_N; ++t) { g_c.wte[h][t] = e[t]/s + 1e-12f; W += g_c.wte[h][t]; }
        for (int t = 0; t < NT_N; ++t) {
            float tau = fmaxf(expf(log_tau[h*NT_N+t]), 1e-6f);
            g_c.inv4tau[h][t] = 1.f/(4.f*tau);
        }
        float bc = fminf(fmaxf(beta[h], 0.5f), 2.5f);
        float neghb = -0.5f*bc;
        float dpc = dp_scale[h]/(8.0f*0.8f);
        float lks = logk_scale[h]*0.6931471805599453f;
        g_c.neghb[h] = neghb;
        g_c.dpl[h]   = lam*dpc;
        g_c.glk[h]   = (1.f-lam)*lks;
        g_c.outs[h]  = out_scale[h];
        int same = 1;
        for (int t = 1; t < NT_N; ++t) if (g_c.inv4tau[h][t] != g_c.inv4tau[h][0]) same = 0;
        g_c.fastf[h] = same;
        g_c.i4t0[h]  = g_c.inv4tau[h][0];
        g_c.fA[h]    = g_c.glk[h]*neghb;
        g_c.fB[h]    = g_c.glk[h]*log2f(W);
    }
    g_c.alpha = 0.1f/(1.f+expf(-dt_logit[0]));
}

// ---------------- GEMM 64x128: C[M,N] = A[M,K] * B[N,K]^T ----------------
__global__ __launch_bounds__(256) void gemm_nt_64x128(const float* __restrict__ A,
        const float* __restrict__ B, float* __restrict__ C, int M, int N, int K) {
    __shared__ float As[16][68];
    __shared__ float Bs[16][132];
    int tid = threadIdx.x;
    int m0 = blockIdx.y*64, n0 = blockIdx.x*128;
    int ty = tid >> 5, tx = tid & 31;          // rows ty*8.., cols tx*4..
    int lr = tid >> 2, lc = (tid & 3)*4;
    const float* Ap = A + (size_t)(m0+lr)*K + lc;
    const float* Bp = B + (size_t)(n0+lr)*K + lc;
    float acc[8][4] = {};
    for (int k0 = 0; k0 < K; k0 += 16) {
        float4 a0 = *(const float4*)(Ap + k0);
        float4 b0 = *(const float4*)(Bp + k0);
        float4 b1 = *(const float4*)(Bp + (size_t)64*K + k0);
        __syncthreads();
        As[lc+0][lr]=a0.x; As[lc+1][lr]=a0.y; As[lc+2][lr]=a0.z; As[lc+3][lr]=a0.w;
        Bs[lc+0][lr]=b0.x; Bs[lc+1][lr]=b0.y; Bs[lc+2][lr]=b0.z; Bs[lc+3][lr]=b0.w;
        Bs[lc+0][lr+64]=b1.x; Bs[lc+1][lr+64]=b1.y; Bs[lc+2][lr+64]=b1.z; Bs[lc+3][lr+64]=b1.w;
        __syncthreads();
        #pragma unroll
        for (int kk = 0; kk < 16; ++kk) {
            float4 a4 = *(const float4*)&As[kk][ty*8];
            float4 a5 = *(const float4*)&As[kk][ty*8+4];
            float4 b4 = *(const float4*)&Bs[kk][tx*4];
            float av[8] = {a4.x,a4.y,a4.z,a4.w,a5.x,a5.y,a5.z,a5.w};
            float bv[4] = {b4.x,b4.y,b4.z,b4.w};
            #pragma unroll
            for (int r = 0; r < 8; ++r)
                #pragma unroll
                for (int c = 0; c < 4; ++c)
                    acc[r][c] = fmaf(av[r], bv[c], acc[r][c]);
        }
    }
    #pragma unroll
    for (int r = 0; r < 8; ++r) {
        int row = m0 + ty*8 + r;
        float4 c0 = {acc[r][0],acc[r][1],acc[r][2],acc[r][3]};
        *(float4*)(C + (size_t)row*N + n0 + tx*4) = c0;
    }
}

__global__ __launch_bounds__(256) void gemm_nt_64(const float* __restrict__ A,
        const float* __restrict__ B, float* __restrict__ C, int M, int N, int K) {
    __shared__ float As[16][68];
    __shared__ float Bs[16][68];
    int tid = threadIdx.x;
    int m0 = blockIdx.y*64, n0 = blockIdx.x*64;
    int ty = tid >> 4, tx = tid & 15;
    int lr = tid >> 2, lc = (tid & 3)*4;
    const float* Ap = A + (size_t)(m0+lr)*K + lc;
    const float* Bp = B + (size_t)(n0+lr)*K + lc;
    float acc[4][4] = {};
    for (int k0 = 0; k0 < K; k0 += 16) {
        float4 a0 = *(const float4*)(Ap + k0);
        float4 b0 = *(const float4*)(Bp + k0);
        __syncthreads();
        As[lc+0][lr]=a0.x; As[lc+1][lr]=a0.y; As[lc+2][lr]=a0.z; As[lc+3][lr]=a0.w;
        Bs[lc+0][lr]=b0.x; Bs[lc+1][lr]=b0.y; Bs[lc+2][lr]=b0.z; Bs[lc+3][lr]=b0.w;
        __syncthreads();
        #pragma unroll
        for (int kk = 0; kk < 16; ++kk) {
            float4 a4 = *(const float4*)&As[kk][ty*4];
            float4 b4 = *(const float4*)&Bs[kk][tx*4];
            float av[4] = {a4.x,a4.y,a4.z,a4.w};
            float bv[4] = {b4.x,b4.y,b4.z,b4.w};
            #pragma unroll
            for (int r = 0; r < 4; ++r)
                #pragma unroll
                for (int c = 0; c < 4; ++c)
                    acc[r][c] = fmaf(av[r], bv[c], acc[r][c]);
        }
    }
    #pragma unroll
    for (int r = 0; r < 4; ++r) {
        int row = m0 + ty*4 + r;
        float4 c0 = {acc[r][0],acc[r][1],acc[r][2],acc[r][3]};
        *(float4*)(C + (size_t)row*N + n0 + tx*4) = c0;
    }
}

// ---------------- reorg: split heads + rmsnorm(g) + g2 ----------------
__global__ __launch_bounds__(256) void reorg_kernel(const float* __restrict__ gnw) {
    int gw = (blockIdx.x*256 + threadIdx.x) >> 5;
    int lane = threadIdx.x & 31;
    if (gw >= T_N*H_N) return;
    int t = gw / H_N, h = gw % H_N;
    const float* row = g_qkvg + (size_t)t*(4*C_N);
    int col = h*D_N + lane*2;
    int o = (h*T_N + t)*D_N + lane*2;
    float2 qv = *(const float2*)(row + col);
    float2 kv = *(const float2*)(row + C_N + col);
    float2 vv = *(const float2*)(row + 2*C_N + col);
    float2 gv = *(const float2*)(row + 3*C_N + col);
    *(float2*)(g_q + o) = qv;
    *(float2*)(g_k + o) = kv;
    *(float2*)(g_v + o) = vv;
    float ss = gv.x*gv.x + gv.y*gv.y;
    #pragma unroll
    for (int m = 16; m; m >>= 1) ss += __shfl_xor_sync(0xffffffffu, ss, m);
    float r = rsqrtf(ss*(1.0f/D_N) + 1e-6f);
    float2 wv = *(const float2*)(gnw + lane*2);
    float g0 = gv.x*r*wv.x, g1 = gv.y*r*wv.y;
    float2 gn = {g0, g1};
    *(float2*)(g_g + o) = gn;
    float s2 = g0*g0 + g1*g1;
    #pragma unroll
    for (int m = 16; m; m >>= 1) s2 += __shfl_xor_sync(0xffffffffu, s2, m);
    if (lane == 0) g_g2[h*T_N + t] = s2;
}

// ---------------- split-j flash attention partial ----------------
#define TILE_F (64*68)
#define ATT_SMEM_BYTES ((6*TILE_F + 128)*4)

__global__ __launch_bounds__(256, 2) void attn_part() {
    extern __shared__ float sm[];
    float* Qs  = sm;
    float* Gis = sm + TILE_F;
    float* Ks  = sm + 2*TILE_F;
    float* Gjs = sm + 3*TILE_F;
    float* Vs  = sm + 4*TILE_F;
    float* Pt  = sm + 5*TILE_F;
    float* g2i = sm + 6*TILE_F;
    float* g2j = g2i + 64;

    int bid = blockIdx.x;
    int h = bid % H_N;
    int u = bid / H_N;
    int it = c_uit[u], cch = c_uc[u];
    int i0 = it * 64;
    int jt0 = cch*4, jt1 = min(jt0+3, it);
    int uidx = c_off[it] + cch;
    int tid = threadIdx.x;
    int ti = tid >> 4, tj = tid & 15;

    int fast = g_c.fastf[h];
    float i4t0 = g_c.i4t0[h], fA = g_c.fA[h], fB = g_c.fB[h];
    float inv4tau[8], wte[8];
    #pragma unroll
    for (int t = 0; t < 8; ++t) { inv4tau[t] = g_c.inv4tau[h][t]; wte[t] = g_c.wte[h][t]; }
    float neghb = g_c.neghb[h], dpl = g_c.dpl[h], glk = g_c.glk[h];

    // load Q & Gi tiles (d-major, transposed)
    const float* qg  = g_q + (size_t)(h*T_N + i0)*D_N;
    const float* gig = g_g + (size_t)(h*T_N + i0)*D_N;
    #pragma unroll
    for (int mm = 0; mm < 4; ++mm) {
        int e = tid + mm*256;
        int r = e >> 4, dc = (e & 15)*4;
        float4 a = *(const float4*)(qg + r*D_N + dc);
        Qs[(dc+0)*68+r]=a.x; Qs[(dc+1)*68+r]=a.y; Qs[(dc+2)*68+r]=a.z; Qs[(dc+3)*68+r]=a.w;
        float4 b = *(const float4*)(gig + r*D_N + dc);
        Gis[(dc+0)*68+r]=b.x; Gis[(dc+1)*68+r]=b.y; Gis[(dc+2)*68+r]=b.z; Gis[(dc+3)*68+r]=b.w;
    }
    if (tid < 64) g2i[tid] = g_g2[h*T_N + i0 + tid];

    float m_r[4], l_r[4], acc[4][4], wii[4];
    #pragma unroll
    for (int r = 0; r < 4; ++r) {
        m_r[r] = -1e30f; l_r[r] = 0.f; wii[r] = 0.f;
        #pragma unroll
        for (int c = 0; c < 4; ++c) acc[r][c] = 0.f;
    }

    for (int jt = jt0; jt <= jt1; ++jt) {
        int j0 = jt*64;
        __syncthreads();
        const float* kg  = g_k + (size_t)(h*T_N + j0)*D_N;
        const float* gjg = g_g + (size_t)(h*T_N + j0)*D_N;
        const float* vg  = g_v + (size_t)(h*T_N + j0)*D_N;
        #pragma unroll
        for (int mm = 0; mm < 4; ++mm) {
            int e = tid + mm*256;
            int r = e >> 4, dc = (e & 15)*4;
            float4 a = *(const float4*)(kg + r*D_N + dc);
            Ks[(dc+0)*68+r]=a.x; Ks[(dc+1)*68+r]=a.y; Ks[(dc+2)*68+r]=a.z; Ks[(dc+3)*68+r]=a.w;
            float4 b = *(const float4*)(gjg + r*D_N + dc);
            Gjs[(dc+0)*68+r]=b.x; Gjs[(dc+1)*68+r]=b.y; Gjs[(dc+2)*68+r]=b.z; Gjs[(dc+3)*68+r]=b.w;
            float4 c4 = *(const float4*)(vg + r*D_N + dc);
            *(float4*)(Vs + r*68 + dc) = c4;
        }
        if (tid < 64) g2j[tid] = g_g2[h*T_N + j0 + tid];
        __syncthreads();

        // score mini-GEMM: dp = q.k, gg = g_i.g_j  (4x4 per thread)
        float dp[4][4] = {}, gg[4][4] = {};
        #pragma unroll 8
        for (int d = 0; d < 64; ++d) {
            float4 qa = *(const float4*)(Qs + d*68 + ti*4);
            float4 kb = *(const float4*)(Ks + d*68 + tj*4);
            float4 ga = *(const float4*)(Gis + d*68 + ti*4);
            float4 gb = *(const float4*)(Gjs + d*68 + tj*4);
            float qv4[4]={qa.x,qa.y,qa.z,qa.w}, kv4[4]={kb.x,kb.y,kb.z,kb.w};
            float gv4[4]={ga.x,ga.y,ga.z,ga.w}, hb4[4]={gb.x,gb.y,gb.z,gb.w};
            #pragma unroll
            for (int r = 0; r < 4; ++r)
                #pragma unroll
                for (int c = 0; c < 4; ++c) {
                    dp[r][c] = fmaf(qv4[r], kv4[c], dp[r][c]);
                    gg[r][c] = fmaf(gv4[r], hb4[c], gg[r][c]);
                }
        }

        // epilogue: blended score per element
        float mt[4];
        if (fast) {
            #pragma unroll
            for (int r = 0; r < 4; ++r) {
                int ig = i0 + ti*4 + r;
                float g2ir = g2i[ti*4+r];
                mt[r] = -1e30f;
                #pragma unroll
                for (int c = 0; c < 4; ++c) {
                    int jg = j0 + tj*4 + c;
                    float bl = -1e30f;
                    if (jg <= ig) {
                        float s = fmaxf(g2ir + g2j[tj*4+c] - 2.f*gg[r][c], 0.f);
                        float uu = fmaf(s, i4t0, 1.f);
                        bl = fmaf(dp[r][c], dpl, fmaf(fA, lg2f_(uu), fB));
                    }
                    dp[r][c] = bl;
                    mt[r] = fmaxf(mt[r], bl);
                }
            }
        } else {
            #pragma unroll
            for (int r = 0; r < 4; ++r) {
                int ig = i0 + ti*4 + r;
                float g2ir = g2i[ti*4+r];
                mt[r] = -1e30f;
                #pragma unroll
                for (int c = 0; c < 4; ++c) {
                    int jg = j0 + tj*4 + c;
                    float bl = -1e30f;
                    if (jg <= ig) {
                        float s = fmaxf(g2ir + g2j[tj*4+c] - 2.f*gg[r][c], 0.f);
                        float Ksum = 0.f;
                        #pragma unroll
                        for (int t = 0; t < 8; ++t) {
                            float uu = fmaf(s, inv4tau[t], 1.f);
                            Ksum = fmaf(wte[t], ex2f_(neghb * lg2f_(uu)), Ksum);
                        }
                        bl = fmaf(dp[r][c], dpl, glk * lg2f_(Ksum));
                    }
                    dp[r][c] = bl;
                    mt[r] = fmaxf(mt[r], bl);
                }
            }
        }
        // online softmax update (row reduce over 16 tj lanes)
        #pragma unroll
        for (int r = 0; r < 4; ++r) {
            #pragma unroll
            for (int o = 8; o; o >>= 1) mt[r] = fmaxf(mt[r], __shfl_xor_sync(0xffffffffu, mt[r], o));
            float mnew = fmaxf(m_r[r], mt[r]);
            float sc = ex2f_((m_r[r]-mnew)*LOG2E);
            m_r[r] = mnew;
            l_r[r] *= sc;
            #pragma unroll
            for (int c = 0; c < 4; ++c) acc[r][c] *= sc;
            float ps = 0.f;
            #pragma unroll
            for (int c = 0; c < 4; ++c) {
                float p = ex2f_((dp[r][c]-mnew)*LOG2E);
                dp[r][c] = p;
                ps += p;
            }
            #pragma unroll
            for (int o = 8; o; o >>= 1) ps += __shfl_xor_sync(0xffffffffu, ps, o);
            l_r[r] += ps;
        }
        if (jt == it && tj == ti) {
            #pragma unroll
            for (int r = 0; r < 4; ++r) wii[r] = dp[r][r];   // diag weight (chunk-local m)
        }
        // write P transposed (xor-swizzled column groups)
        #pragma unroll
        for (int c = 0; c < 4; ++c) {
            int lj = tj*4 + c;
            int sg = (ti ^ lj) & 15;
            #pragma unroll
            for (int r = 0; r < 4; ++r) Pt[lj*68 + sg*4 + r] = dp[r][c];
        }
        __syncthreads();
        // PV accumulate
        #pragma unroll 4
        for (int j = 0; j < 64; ++j) {
            int sg = (ti ^ j) & 15;
            float4 pv = *(const float4*)(Pt + j*68 + sg*4);
            float4 vv = *(const float4*)(Vs + j*68 + tj*4);
            float pa[4]={pv.x,pv.y,pv.z,pv.w}, vb[4]={vv.x,vv.y,vv.z,vv.w};
            #pragma unroll
            for (int r = 0; r < 4; ++r)
                #pragma unroll
                for (int c = 0; c < 4; ++c)
                    acc[r][c] = fmaf(pa[r], vb[c], acc[r][c]);
        }
    }

    // write partials
    int base = (h*40 + uidx)*64;
    if (tj == 0) {
        #pragma unroll
        for (int r = 0; r < 4; ++r) {
            g_pm[base + ti*4 + r] = m_r[r];
            g_pl[base + ti*4 + r] = l_r[r];
        }
    }
    #pragma unroll
    for (int r = 0; r < 4; ++r) {
        float4 a4 = {acc[r][0], acc[r][1], acc[r][2], acc[r][3]};
        *(float4*)(g_pacc + (size_t)(base + ti*4 + r)*64 + tj*4) = a4;
    }
    if (jt1 == it && tj == ti) {
        #pragma unroll
        for (int r = 0; r < 4; ++r) g_dw[(h*16 + it)*64 + ti*4 + r] = wii[r];
    }
}

// ---------------- combine partials -> g_y ----------------
__global__ __launch_bounds__(256) void attn_combine() {
    int bid = blockIdx.x;               // 192 = h-major? use h = bid%12
    int h = bid % H_N, it = bid / H_N;
    int i0 = it * 64;
    int nc = it/4 + 1;
    int tid = threadIdx.x;
    int row = tid >> 2;
    int c0 = (tid & 3) * 16;
    int b0 = (h*40 + c_off[it])*64 + row;

    float mv[4], sc4[4];
    float gm = -1e30f;
    for (int c = 0; c < nc; ++c) { mv[c] = g_pm[b0 + c*64]; gm = fmaxf(gm, mv[c]); }
    float L = 0.f;
    for (int c = 0; c < nc; ++c) {
        sc4[c] = ex2f_((mv[c]-gm)*LOG2E);
        L += g_pl[b0 + c*64] * sc4[c];
    }
    float linv = 1.f / fmaxf(L, 1e-12f);
    float pii = g_dw[(h*16 + it)*64 + row] * sc4[nc-1] * linv;
    float alpha = g_c.alpha;
    float ca = 1.f - alpha;
    float cb = alpha / (1.f + pii);
    float outs = g_c.outs[h];

    for (int cc = 0; cc < 16; cc += 4) {
        float ax=0.f, ay=0.f, az=0.f, aw=0.f;
        for (int c = 0; c < nc; ++c) {
            float4 p = *(const float4*)(g_pacc + (size_t)(b0 + c*64)*64 + c0 + cc);
            float s = sc4[c];
            ax = fmaf(p.x, s, ax); ay = fmaf(p.y, s, ay);
            az = fmaf(p.z, s, az); aw = fmaf(p.w, s, aw);
        }
        float4 v = *(const float4*)(g_v + (size_t)(h*T_N + i0 + row)*D_N + c0 + cc);
        float4 o;
        float p0 = ax*linv, p1 = ay*linv, p2 = az*linv, p3 = aw*linv;
        o.x = outs * (ca*p0 + cb*(p0 + pii*v.x));
        o.y = outs * (ca*p1 + cb*(p1 + pii*v.y));
        o.z = outs * (ca*p2 + cb*(p2 + pii*v.z));
        o.w = outs * (ca*p3 + cb*(p3 + pii*v.w));
        *(float4*)(g_y + (size_t)(i0 + row)*C_N + h*D_N + c0 + cc) = o;
    }
}

// ---------------- launch ----------------
extern "C" void kernel_launch(void* const* d_in, const int* in_sizes, int n_in,
                              void* d_out, int out_size) {
    const float* x         = (const float*)d_in[0];
    const float* W_qkvg    = (const float*)d_in[1];
    const float* W_out     = (const float*)d_in[2];
    const float* lam       = (const float*)d_in[3];
    const float* log_tau   = (const float*)d_in[4];
    const float* logit_w   = (const float*)d_in[5];
    const float* beta      = (const float*)d_in[6];
    const float* out_scale = (const float*)d_in[7];
    const float* dp_scale  = (const float*)d_in[8];
    const float* logk_sc   = (const float*)d_in[9];
    const float* dt_logit  = (const float*)d_in[10];
    const float* gnw       = (const float*)d_in[11];
    float* out = (float*)d_out;

    float *qkvg_p = nullptr, *y_p = nullptr;
    cudaGetSymbolAddress((void**)&qkvg_p, g_qkvg);
    cudaGetSymbolAddress((void**)&y_p, g_y);

    cudaFuncSetAttribute(attn_part, cudaFuncAttributeMaxDynamicSharedMemorySize, ATT_SMEM_BYTES);

    const_kernel<<<1, 32>>>(lam, log_tau, logit_w, beta, out_scale, dp_scale, logk_sc, dt_logit);
    gemm_nt_64x128<<<dim3(3072/128, 1024/64), 256>>>(x, W_qkvg, qkvg_p, T_N, 4*C_N, C_N);
    reorg_kernel<<<(T_N*H_N*32)/256, 256>>>(gnw);
    attn_part<<<480, 256, ATT_SMEM_BYTES>>>();
    attn_combine<<<192, 256>>>();
    gemm_nt_64<<<dim3(768/64, 1024/64), 256>>>(y_p, W_out, out, T_N, C_N, C_N);
}

// round 3
// speedup vs baseline: 1.8262x; 1.4191x over previous
#include <cuda_runtime.h>
#include <cuda_bf16.h>

#define T_N 1024
#define C_N 768
#define H_N 12
#define D_N 64
#define NT_N 8
#define LOG2E 1.4426950408889634f

// ---------------- scratch (static device globals; no allocation) ----------------
__device__ float g_qkvg[T_N * 4 * C_N];      // [T][3072]
__device__ float g_q[H_N * T_N * D_N];       // [H][T][D]
__device__ float g_k[H_N * T_N * D_N];
__device__ float g_v[H_N * T_N * D_N];
__device__ float g_g[H_N * T_N * D_N];       // rmsnormed g
__device__ float g_g2[H_N * T_N];            // ||g||^2 per (h,t)
__device__ float g_y[T_N * C_N];             // attention out, [T][C] layout

// split-j partials: 40 units per head (chunks of <=4 j-tiles)
__device__ float g_pacc[H_N * 40 * 64 * 64]; // [h][unit][row][col]
__device__ float g_pm[H_N * 40 * 64];
__device__ float g_pl[H_N * 40 * 64];
__device__ float g_dw[H_N * 16 * 64];        // diag weights per (h,it,row)

// unit tables: heavy (4-tile) units first for scheduling
__constant__ int c_uit[40] = {15,15,15,15,14,14,14,13,13,13,12,12,12,11,11,11,10,10,9,9,8,8,7,7,6,5,4,3,
                              14,10,6,2, 13,9,5,1, 12,8,4,0};
__constant__ int c_uc[40]  = { 0, 1, 2, 3, 0, 1, 2, 0, 1, 2, 0, 1, 2, 0, 1, 2, 0, 1,0,1,0,1,0,1,0,0,0,0,
                               3, 2,1,0,  3,2,1,0,  3,2,1,0};
__constant__ int c_off[16] = {0,1,2,3,4,6,8,10,12,15,18,21,24,28,32,36};

struct Consts {
    float inv4tau[H_N][NT_N];
    float wte[H_N][NT_N];     // softmax(logit_w) + 1e-12
    float neghb[H_N];         // -(clip(beta)/2)
    float dpl[H_N];           // lam * dp_scale/(8*0.8)
    float glk[H_N];           // (1-lam) * logk_scale * ln2
    float outs[H_N];
    float fA[H_N], fB[H_N], i4t0[H_N];
    int   fastf[H_N];
    float alpha;
};
__device__ Consts g_c;

__device__ __forceinline__ float ex2f_(float x){ float y; asm("ex2.approx.ftz.f32 %0, %1;":"=f"(y):"f"(x)); return y; }
__device__ __forceinline__ float lg2f_(float x){ float y; asm("lg2.approx.ftz.f32 %0, %1;":"=f"(y):"f"(x)); return y; }
__device__ __forceinline__ unsigned f2tf32(float x){ unsigned y; asm("cvt.rna.tf32.f32 %0, %1;":"=r"(y):"f"(x)); return y; }

__device__ __forceinline__ void mma_tf32(float* d, const unsigned* a, const unsigned* b) {
    asm volatile(
      "mma.sync.aligned.m16n8k8.row.col.f32.tf32.tf32.f32 "
      "{%0,%1,%2,%3}, {%4,%5,%6,%7}, {%8,%9}, {%0,%1,%2,%3};\n"
      : "+f"(d[0]), "+f"(d[1]), "+f"(d[2]), "+f"(d[3])
      : "r"(a[0]), "r"(a[1]), "r"(a[2]), "r"(a[3]), "r"(b[0]), "r"(b[1]));
}

// ---------------- constants precompute ----------------
__global__ void const_kernel(const float* lam_p, const float* log_tau,
                             const float* logit_w, const float* beta,
                             const float* out_scale, const float* dp_scale,
                             const float* logk_scale, const float* dt_logit) {
    if (threadIdx.x != 0 || blockIdx.x != 0) return;
    float lam = lam_p[0];
    for (int h = 0; h < H_N; ++h) {
        float mx = -1e30f;
        for (int t = 0; t < NT_N; ++t) mx = fmaxf(mx, logit_w[h*NT_N+t]);
        float s = 0.f, e[NT_N];
        for (int t = 0; t < NT_N; ++t) { e[t] = expf(logit_w[h*NT_N+t]-mx); s += e[t]; }
        float W = 0.f;
        for (int t = 0; t < NT_N; ++t) { g_c.wte[h][t] = e[t]/s + 1e-12f; W += g_c.wte[h][t]; }
        for (int t = 0; t < NT_N; ++t) {
            float tau = fmaxf(expf(log_tau[h*NT_N+t]), 1e-6f);
            g_c.inv4tau[h][t] = 1.f/(4.f*tau);
        }
        float bc = fminf(fmaxf(beta[h], 0.5f), 2.5f);
        float neghb = -0.5f*bc;
        float dpc = dp_scale[h]/(8.0f*0.8f);
        float lks = logk_scale[h]*0.6931471805599453f;
        g_c.neghb[h] = neghb;
        g_c.dpl[h]   = lam*dpc;
        g_c.glk[h]   = (1.f-lam)*lks;
        g_c.outs[h]  = out_scale[h];
        int same = 1;
        for (int t = 1; t < NT_N; ++t) if (g_c.inv4tau[h][t] != g_c.inv4tau[h][0]) same = 0;
        g_c.fastf[h] = same;
        g_c.i4t0[h]  = g_c.inv4tau[h][0];
        g_c.fA[h]    = g_c.glk[h]*neghb;
        g_c.fB[h]    = g_c.glk[h]*log2f(W);
    }
    g_c.alpha = 0.1f/(1.f+expf(-dt_logit[0]));
}

// ---------------- tf32 tensor-core GEMM: C[M,N] = A[M,K] * B[N,K]^T ----------------
// 128x128 CTA tile, kblock 32, 8 warps (2m x 4n), warp tile 64x32 via m16n8k8.
#define GS 36   // smem row stride (words); (4r+c) mod 32 distinct -> conflict-free frags

__global__ __launch_bounds__(256, 2) void gemm_tf32(const float* __restrict__ A,
        const float* __restrict__ B, float* __restrict__ C, int M, int N, int K) {
    __shared__ unsigned As[128*GS];
    __shared__ unsigned Bs[128*GS];
    int tid = threadIdx.x;
    int lane = tid & 31, w = tid >> 5;
    int wm = w >> 2, wn = w & 3;
    int m0 = blockIdx.y*128, n0 = blockIdx.x*128;
    int lr = tid >> 3, lc = (tid & 7)*4;   // 32 rows x 32 cols per pass, 4 passes
    const float* Ap = A + (size_t)(m0+lr)*K + lc;
    const float* Bp = B + (size_t)(n0+lr)*K + lc;

    float acc[4][4][4];
    #pragma unroll
    for (int i = 0; i < 4; ++i)
        #pragma unroll
        for (int j = 0; j < 4; ++j)
            #pragma unroll
            for (int v = 0; v < 4; ++v) acc[i][j][v] = 0.f;

    int qa = lane >> 2, ra = lane & 3;     // fragment row/col ids

    for (int kb = 0; kb < K; kb += 32) {
        __syncthreads();
        #pragma unroll
        for (int p = 0; p < 4; ++p) {
            float4 a = *(const float4*)(Ap + (size_t)p*32*K + kb);
            float4 b = *(const float4*)(Bp + (size_t)p*32*K + kb);
            unsigned* as = As + (lr + p*32)*GS + lc;
            unsigned* bs = Bs + (lr + p*32)*GS + lc;
            as[0]=f2tf32(a.x); as[1]=f2tf32(a.y); as[2]=f2tf32(a.z); as[3]=f2tf32(a.w);
            bs[0]=f2tf32(b.x); bs[1]=f2tf32(b.y); bs[2]=f2tf32(b.z); bs[3]=f2tf32(b.w);
        }
        __syncthreads();
        #pragma unroll
        for (int ks = 0; ks < 4; ++ks) {
            unsigned af[4][4], bf[4][2];
            #pragma unroll
            for (int mt = 0; mt < 4; ++mt) {
                const unsigned* p = As + (wm*64 + mt*16 + qa)*GS + ks*8 + ra;
                af[mt][0] = p[0];
                af[mt][1] = p[8*GS];
                af[mt][2] = p[4];
                af[mt][3] = p[8*GS + 4];
            }
            #pragma unroll
            for (int nt = 0; nt < 4; ++nt) {
                const unsigned* p = Bs + (wn*32 + nt*8 + qa)*GS + ks*8 + ra;
                bf[nt][0] = p[0];
                bf[nt][1] = p[4];
            }
            #pragma unroll
            for (int mt = 0; mt < 4; ++mt)
                #pragma unroll
                for (int nt = 0; nt < 4; ++nt)
                    mma_tf32(acc[mt][nt], af[mt], bf[nt]);
        }
    }

    // epilogue
    #pragma unroll
    for (int mt = 0; mt < 4; ++mt) {
        int row = m0 + wm*64 + mt*16 + qa;
        #pragma unroll
        for (int nt = 0; nt < 4; ++nt) {
            int col = n0 + wn*32 + nt*8 + ra*2;
            float2 c0 = {acc[mt][nt][0], acc[mt][nt][1]};
            float2 c1 = {acc[mt][nt][2], acc[mt][nt][3]};
            *(float2*)(C + (size_t)row*N + col) = c0;
            *(float2*)(C + (size_t)(row+8)*N + col) = c1;
        }
    }
}

// ---------------- reorg: split heads + rmsnorm(g) + g2 ----------------
__global__ __launch_bounds__(256) void reorg_kernel(const float* __restrict__ gnw) {
    int gw = (blockIdx.x*256 + threadIdx.x) >> 5;
    int lane = threadIdx.x & 31;
    if (gw >= T_N*H_N) return;
    int t = gw / H_N, h = gw % H_N;
    const float* row = g_qkvg + (size_t)t*(4*C_N);
    int col = h*D_N + lane*2;
    int o = (h*T_N + t)*D_N + lane*2;
    float2 qv = *(const float2*)(row + col);
    float2 kv = *(const float2*)(row + C_N + col);
    float2 vv = *(const float2*)(row + 2*C_N + col);
    float2 gv = *(const float2*)(row + 3*C_N + col);
    *(float2*)(g_q + o) = qv;
    *(float2*)(g_k + o) = kv;
    *(float2*)(g_v + o) = vv;
    float ss = gv.x*gv.x + gv.y*gv.y;
    #pragma unroll
    for (int m = 16; m; m >>= 1) ss += __shfl_xor_sync(0xffffffffu, ss, m);
    float r = rsqrtf(ss*(1.0f/D_N) + 1e-6f);
    float2 wv = *(const float2*)(gnw + lane*2);
    float g0 = gv.x*r*wv.x, g1 = gv.y*r*wv.y;
    float2 gn = {g0, g1};
    *(float2*)(g_g + o) = gn;
    float s2 = g0*g0 + g1*g1;
    #pragma unroll
    for (int m = 16; m; m >>= 1) s2 += __shfl_xor_sync(0xffffffffu, s2, m);
    if (lane == 0) g_g2[h*T_N + t] = s2;
}

// ---------------- split-j flash attention partial ----------------
#define TILE_F (64*68)
#define ATT_SMEM_BYTES ((6*TILE_F + 128)*4)

__global__ __launch_bounds__(256, 2) void attn_part() {
    extern __shared__ float sm[];
    float* Qs  = sm;
    float* Gis = sm + TILE_F;
    float* Ks  = sm + 2*TILE_F;
    float* Gjs = sm + 3*TILE_F;
    float* Vs  = sm + 4*TILE_F;
    float* Pt  = sm + 5*TILE_F;
    float* g2i = sm + 6*TILE_F;
    float* g2j = g2i + 64;

    int bid = blockIdx.x;
    int h = bid % H_N;
    int u = bid / H_N;
    int it = c_uit[u], cch = c_uc[u];
    int i0 = it * 64;
    int jt0 = cch*4, jt1 = min(jt0+3, it);
    int uidx = c_off[it] + cch;
    int tid = threadIdx.x;
    int ti = tid >> 4, tj = tid & 15;

    int fast = g_c.fastf[h];
    float i4t0 = g_c.i4t0[h], fA = g_c.fA[h], fB = g_c.fB[h];
    float inv4tau[8], wte[8];
    #pragma unroll
    for (int t = 0; t < 8; ++t) { inv4tau[t] = g_c.inv4tau[h][t]; wte[t] = g_c.wte[h][t]; }
    float neghb = g_c.neghb[h], dpl = g_c.dpl[h], glk = g_c.glk[h];

    // load Q & Gi tiles (d-major, transposed)
    const float* qg  = g_q + (size_t)(h*T_N + i0)*D_N;
    const float* gig = g_g + (size_t)(h*T_N + i0)*D_N;
    #pragma unroll
    for (int mm = 0; mm < 4; ++mm) {
        int e = tid + mm*256;
        int r = e >> 4, dc = (e & 15)*4;
        float4 a = *(const float4*)(qg + r*D_N + dc);
        Qs[(dc+0)*68+r]=a.x; Qs[(dc+1)*68+r]=a.y; Qs[(dc+2)*68+r]=a.z; Qs[(dc+3)*68+r]=a.w;
        float4 b = *(const float4*)(gig + r*D_N + dc);
        Gis[(dc+0)*68+r]=b.x; Gis[(dc+1)*68+r]=b.y; Gis[(dc+2)*68+r]=b.z; Gis[(dc+3)*68+r]=b.w;
    }
    if (tid < 64) g2i[tid] = g_g2[h*T_N + i0 + tid];

    float m_r[4], l_r[4], acc[4][4], wii[4];
    #pragma unroll
    for (int r = 0; r < 4; ++r) {
        m_r[r] = -1e30f; l_r[r] = 0.f; wii[r] = 0.f;
        #pragma unroll
        for (int c = 0; c < 4; ++c) acc[r][c] = 0.f;
    }

    for (int jt = jt0; jt <= jt1; ++jt) {
        int j0 = jt*64;
        __syncthreads();
        const float* kg  = g_k + (size_t)(h*T_N + j0)*D_N;
        const float* gjg = g_g + (size_t)(h*T_N + j0)*D_N;
        const float* vg  = g_v + (size_t)(h*T_N + j0)*D_N;
        #pragma unroll
        for (int mm = 0; mm < 4; ++mm) {
            int e = tid + mm*256;
            int r = e >> 4, dc = (e & 15)*4;
            float4 a = *(const float4*)(kg + r*D_N + dc);
            Ks[(dc+0)*68+r]=a.x; Ks[(dc+1)*68+r]=a.y; Ks[(dc+2)*68+r]=a.z; Ks[(dc+3)*68+r]=a.w;
            float4 b = *(const float4*)(gjg + r*D_N + dc);
            Gjs[(dc+0)*68+r]=b.x; Gjs[(dc+1)*68+r]=b.y; Gjs[(dc+2)*68+r]=b.z; Gjs[(dc+3)*68+r]=b.w;
            float4 c4 = *(const float4*)(vg + r*D_N + dc);
            *(float4*)(Vs + r*68 + dc) = c4;
        }
        if (tid < 64) g2j[tid] = g_g2[h*T_N + j0 + tid];
        __syncthreads();

        // score mini-GEMM: dp = q.k, gg = g_i.g_j  (4x4 per thread)
        float dp[4][4] = {}, gg[4][4] = {};
        #pragma unroll 8
        for (int d = 0; d < 64; ++d) {
            float4 qa = *(const float4*)(Qs + d*68 + ti*4);
            float4 kb = *(const float4*)(Ks + d*68 + tj*4);
            float4 ga = *(const float4*)(Gis + d*68 + ti*4);
            float4 gb = *(const float4*)(Gjs + d*68 + tj*4);
            float qv4[4]={qa.x,qa.y,qa.z,qa.w}, kv4[4]={kb.x,kb.y,kb.z,kb.w};
            float gv4[4]={ga.x,ga.y,ga.z,ga.w}, hb4[4]={gb.x,gb.y,gb.z,gb.w};
            #pragma unroll
            for (int r = 0; r < 4; ++r)
                #pragma unroll
                for (int c = 0; c < 4; ++c) {
                    dp[r][c] = fmaf(qv4[r], kv4[c], dp[r][c]);
                    gg[r][c] = fmaf(gv4[r], hb4[c], gg[r][c]);
                }
        }

        // epilogue: blended score per element
        float mt[4];
        if (fast) {
            #pragma unroll
            for (int r = 0; r < 4; ++r) {
                int ig = i0 + ti*4 + r;
                float g2ir = g2i[ti*4+r];
                mt[r] = -1e30f;
                #pragma unroll
                for (int c = 0; c < 4; ++c) {
                    int jg = j0 + tj*4 + c;
                    float bl = -1e30f;
                    if (jg <= ig) {
                        float s = fmaxf(g2ir + g2j[tj*4+c] - 2.f*gg[r][c], 0.f);
                        float uu = fmaf(s, i4t0, 1.f);
                        bl = fmaf(dp[r][c], dpl, fmaf(fA, lg2f_(uu), fB));
                    }
                    dp[r][c] = bl;
                    mt[r] = fmaxf(mt[r], bl);
                }
            }
        } else {
            #pragma unroll
            for (int r = 0; r < 4; ++r) {
                int ig = i0 + ti*4 + r;
                float g2ir = g2i[ti*4+r];
                mt[r] = -1e30f;
                #pragma unroll
                for (int c = 0; c < 4; ++c) {
                    int jg = j0 + tj*4 + c;
                    float bl = -1e30f;
                    if (jg <= ig) {
                        float s = fmaxf(g2ir + g2j[tj*4+c] - 2.f*gg[r][c], 0.f);
                        float Ksum = 0.f;
                        #pragma unroll
                        for (int t = 0; t < 8; ++t) {
                            float uu = fmaf(s, inv4tau[t], 1.f);
                            Ksum = fmaf(wte[t], ex2f_(neghb * lg2f_(uu)), Ksum);
                        }
                        bl = fmaf(dp[r][c], dpl, glk * lg2f_(Ksum));
                    }
                    dp[r][c] = bl;
                    mt[r] = fmaxf(mt[r], bl);
                }
            }
        }
        // online softmax update (row reduce over 16 tj lanes)
        #pragma unroll
        for (int r = 0; r < 4; ++r) {
            #pragma unroll
            for (int o = 8; o; o >>= 1) mt[r] = fmaxf(mt[r], __shfl_xor_sync(0xffffffffu, mt[r], o));
            float mnew = fmaxf(m_r[r], mt[r]);
            float sc = ex2f_((m_r[r]-mnew)*LOG2E);
            m_r[r] = mnew;
            l_r[r] *= sc;
            #pragma unroll
            for (int c = 0; c < 4; ++c) acc[r][c] *= sc;
            float ps = 0.f;
            #pragma unroll
            for (int c = 0; c < 4; ++c) {
                float p = ex2f_((dp[r][c]-mnew)*LOG2E);
                dp[r][c] = p;
                ps += p;
            }
            #pragma unroll
            for (int o = 8; o; o >>= 1) ps += __shfl_xor_sync(0xffffffffu, ps, o);
            l_r[r] += ps;
        }
        if (jt == it && tj == ti) {
            #pragma unroll
            for (int r = 0; r < 4; ++r) wii[r] = dp[r][r];   // diag weight (chunk-local m)
        }
        // write P transposed (xor-swizzled column groups)
        #pragma unroll
        for (int c = 0; c < 4; ++c) {
            int lj = tj*4 + c;
            int sg = (ti ^ lj) & 15;
            #pragma unroll
            for (int r = 0; r < 4; ++r) Pt[lj*68 + sg*4 + r] = dp[r][c];
        }
        __syncthreads();
        // PV accumulate
        #pragma unroll 4
        for (int j = 0; j < 64; ++j) {
            int sg = (ti ^ j) & 15;
            float4 pv = *(const float4*)(Pt + j*68 + sg*4);
            float4 vv = *(const float4*)(Vs + j*68 + tj*4);
            float pa[4]={pv.x,pv.y,pv.z,pv.w}, vb[4]={vv.x,vv.y,vv.z,vv.w};
            #pragma unroll
            for (int r = 0; r < 4; ++r)
                #pragma unroll
                for (int c = 0; c < 4; ++c)
                    acc[r][c] = fmaf(pa[r], vb[c], acc[r][c]);
        }
    }

    // write partials
    int base = (h*40 + uidx)*64;
    if (tj == 0) {
        #pragma unroll
        for (int r = 0; r < 4; ++r) {
            g_pm[base + ti*4 + r] = m_r[r];
            g_pl[base + ti*4 + r] = l_r[r];
        }
    }
    #pragma unroll
    for (int r = 0; r < 4; ++r) {
        float4 a4 = {acc[r][0], acc[r][1], acc[r][2], acc[r][3]};
        *(float4*)(g_pacc + (size_t)(base + ti*4 + r)*64 + tj*4) = a4;
    }
    if (jt1 == it && tj == ti) {
        #pragma unroll
        for (int r = 0; r < 4; ++r) g_dw[(h*16 + it)*64 + ti*4 + r] = wii[r];
    }
}

// ---------------- combine partials -> g_y ----------------
__global__ __launch_bounds__(256) void attn_combine() {
    int bid = blockIdx.x;
    int h = bid % H_N, it = bid / H_N;
    int i0 = it * 64;
    int nc = it/4 + 1;
    int tid = threadIdx.x;
    int row = tid >> 2;
    int c0 = (tid & 3) * 16;
    int b0 = (h*40 + c_off[it])*64 + row;

    float mv[4], sc4[4];
    float gm = -1e30f;
    for (int c = 0; c < nc; ++c) { mv[c] = g_pm[b0 + c*64]; gm = fmaxf(gm, mv[c]); }
    float L = 0.f;
    for (int c = 0; c < nc; ++c) {
        sc4[c] = ex2f_((mv[c]-gm)*LOG2E);
        L += g_pl[b0 + c*64] * sc4[c];
    }
    float linv = 1.f / fmaxf(L, 1e-12f);
    float pii = g_dw[(h*16 + it)*64 + row] * sc4[nc-1] * linv;
    float alpha = g_c.alpha;
    float ca = 1.f - alpha;
    float cb = alpha / (1.f + pii);
    float outs = g_c.outs[h];

    for (int cc = 0; cc < 16; cc += 4) {
        float ax=0.f, ay=0.f, az=0.f, aw=0.f;
        for (int c = 0; c < nc; ++c) {
            float4 p = *(const float4*)(g_pacc + (size_t)(b0 + c*64)*64 + c0 + cc);
            float s = sc4[c];
            ax = fmaf(p.x, s, ax); ay = fmaf(p.y, s, ay);
            az = fmaf(p.z, s, az); aw = fmaf(p.w, s, aw);
        }
        float4 v = *(const float4*)(g_v + (size_t)(h*T_N + i0 + row)*D_N + c0 + cc);
        float4 o;
        float p0 = ax*linv, p1 = ay*linv, p2 = az*linv, p3 = aw*linv;
        o.x = outs * (ca*p0 + cb*(p0 + pii*v.x));
        o.y = outs * (ca*p1 + cb*(p1 + pii*v.y));
        o.z = outs * (ca*p2 + cb*(p2 + pii*v.z));
        o.w = outs * (ca*p3 + cb*(p3 + pii*v.w));
        *(float4*)(g_y + (size_t)(i0 + row)*C_N + h*D_N + c0 + cc) = o;
    }
}

// ---------------- launch ----------------
extern "C" void kernel_launch(void* const* d_in, const int* in_sizes, int n_in,
                              void* d_out, int out_size) {
    const float* x         = (const float*)d_in[0];
    const float* W_qkvg    = (const float*)d_in[1];
    const float* W_out     = (const float*)d_in[2];
    const float* lam       = (const float*)d_in[3];
    const float* log_tau   = (const float*)d_in[4];
    const float* logit_w   = (const float*)d_in[5];
    const float* beta      = (const float*)d_in[6];
    const float* out_scale = (const float*)d_in[7];
    const float* dp_scale  = (const float*)d_in[8];
    const float* logk_sc   = (const float*)d_in[9];
    const float* dt_logit  = (const float*)d_in[10];
    const float* gnw       = (const float*)d_in[11];
    float* out = (float*)d_out;

    float *qkvg_p = nullptr, *y_p = nullptr;
    cudaGetSymbolAddress((void**)&qkvg_p, g_qkvg);
    cudaGetSymbolAddress((void**)&y_p, g_y);

    cudaFuncSetAttribute(attn_part, cudaFuncAttributeMaxDynamicSharedMemorySize, ATT_SMEM_BYTES);

    const_kernel<<<1, 32>>>(lam, log_tau, logit_w, beta, out_scale, dp_scale, logk_sc, dt_logit);
    gemm_tf32<<<dim3(3072/128, 1024/128), 256>>>(x, W_qkvg, qkvg_p, T_N, 4*C_N, C_N);
    reorg_kernel<<<(T_N*H_N*32)/256, 256>>>(gnw);
    attn_part<<<480, 256, ATT_SMEM_BYTES>>>();
    attn_combine<<<192, 256>>>();
    gemm_tf32<<<dim3(768/128, 1024/128), 256>>>(y_p, W_out, out, T_N, C_N, C_N);
}

// round 4
// speedup vs baseline: 2.4196x; 1.3250x over previous
#include <cuda_runtime.h>
#include <cuda_bf16.h>

#define T_N 1024
#define C_N 768
#define H_N 12
#define D_N 64
#define NT_N 8
#define LOG2E 1.4426950408889634f

// ---------------- scratch (static device globals; no allocation) ----------------
__device__ float g_qkvg[T_N * 4 * C_N];      // [T][3072]
__device__ float g_q[H_N * T_N * D_N];       // [H][T][D]
__device__ float g_k[H_N * T_N * D_N];
__device__ float g_v[H_N * T_N * D_N];
__device__ float g_g[H_N * T_N * D_N];       // rmsnormed g
__device__ float g_g2[H_N * T_N];            // ||g||^2 per (h,t)
__device__ float g_y[T_N * C_N];             // attention out, [T][C] layout

// split-j partials: 40 units per head (chunks of <=4 j-tiles)
__device__ float g_pacc[H_N * 40 * 64 * 64]; // [h][unit][row][col]
__device__ float g_pm[H_N * 40 * 64];
__device__ float g_pl[H_N * 40 * 64];
__device__ float g_dw[H_N * 16 * 64];        // diag weights per (h,it,row)

// unit tables: heavy (4-tile) units first for scheduling
__constant__ int c_uit[40] = {15,15,15,15,14,14,14,13,13,13,12,12,12,11,11,11,10,10,9,9,8,8,7,7,6,5,4,3,
                              14,10,6,2, 13,9,5,1, 12,8,4,0};
__constant__ int c_uc[40]  = { 0, 1, 2, 3, 0, 1, 2, 0, 1, 2, 0, 1, 2, 0, 1, 2, 0, 1,0,1,0,1,0,1,0,0,0,0,
                               3, 2,1,0,  3,2,1,0,  3,2,1,0};
__constant__ int c_off[16] = {0,1,2,3,4,6,8,10,12,15,18,21,24,28,32,36};

struct Consts {
    float inv4tau[H_N][NT_N];
    float wte[H_N][NT_N];     // softmax(logit_w) + 1e-12
    float neghb[H_N];         // -(clip(beta)/2)
    float dpl[H_N];           // lam * dp_scale/(8*0.8)
    float glk[H_N];           // (1-lam) * logk_scale * ln2
    float outs[H_N];
    float fA[H_N], fB[H_N], i4t0[H_N];
    int   fastf[H_N];
    float alpha;
};
__device__ Consts g_c;

__device__ __forceinline__ float ex2f_(float x){ float y; asm("ex2.approx.ftz.f32 %0, %1;":"=f"(y):"f"(x)); return y; }
__device__ __forceinline__ float lg2f_(float x){ float y; asm("lg2.approx.ftz.f32 %0, %1;":"=f"(y):"f"(x)); return y; }
__device__ __forceinline__ unsigned f2tf32(float x){ unsigned y; asm("cvt.rna.tf32.f32 %0, %1;":"=r"(y):"f"(x)); return y; }

__device__ __forceinline__ void mma_tf32(float* d, const unsigned* a, const unsigned* b) {
    asm volatile(
      "mma.sync.aligned.m16n8k8.row.col.f32.tf32.tf32.f32 "
      "{%0,%1,%2,%3}, {%4,%5,%6,%7}, {%8,%9}, {%0,%1,%2,%3};\n"
      : "+f"(d[0]), "+f"(d[1]), "+f"(d[2]), "+f"(d[3])
      : "r"(a[0]), "r"(a[1]), "r"(a[2]), "r"(a[3]), "r"(b[0]), "r"(b[1]));
}

// ---------------- constants precompute ----------------
__global__ void const_kernel(const float* lam_p, const float* log_tau,
                             const float* logit_w, const float* beta,
                             const float* out_scale, const float* dp_scale,
                             const float* logk_scale, const float* dt_logit) {
    if (threadIdx.x != 0 || blockIdx.x != 0) return;
    float lam = lam_p[0];
    for (int h = 0; h < H_N; ++h) {
        float mx = -1e30f;
        for (int t = 0; t < NT_N; ++t) mx = fmaxf(mx, logit_w[h*NT_N+t]);
        float s = 0.f, e[NT_N];
        for (int t = 0; t < NT_N; ++t) { e[t] = expf(logit_w[h*NT_N+t]-mx); s += e[t]; }
        float W = 0.f;
        for (int t = 0; t < NT_N; ++t) { g_c.wte[h][t] = e[t]/s + 1e-12f; W += g_c.wte[h][t]; }
        for (int t = 0; t < NT_N; ++t) {
            float tau = fmaxf(expf(log_tau[h*NT_N+t]), 1e-6f);
            g_c.inv4tau[h][t] = 1.f/(4.f*tau);
        }
        float bc = fminf(fmaxf(beta[h], 0.5f), 2.5f);
        float neghb = -0.5f*bc;
        float dpc = dp_scale[h]/(8.0f*0.8f);
        float lks = logk_scale[h]*0.6931471805599453f;
        g_c.neghb[h] = neghb;
        g_c.dpl[h]   = lam*dpc;
        g_c.glk[h]   = (1.f-lam)*lks;
        g_c.outs[h]  = out_scale[h];
        int same = 1;
        for (int t = 1; t < NT_N; ++t) if (g_c.inv4tau[h][t] != g_c.inv4tau[h][0]) same = 0;
        g_c.fastf[h] = same;
        g_c.i4t0[h]  = g_c.inv4tau[h][0];
        g_c.fA[h]    = g_c.glk[h]*neghb;
        g_c.fB[h]    = g_c.glk[h]*log2f(W);
    }
    g_c.alpha = 0.1f/(1.f+expf(-dt_logit[0]));
}

// ---------------- tf32 tensor-core GEMM: C[M,N] = A[M,K] * B[N,K]^T ----------------
#define GS 36

__global__ __launch_bounds__(256, 2) void gemm_tf32(const float* __restrict__ A,
        const float* __restrict__ B, float* __restrict__ C, int M, int N, int K) {
    __shared__ unsigned As[128*GS];
    __shared__ unsigned Bs[128*GS];
    int tid = threadIdx.x;
    int lane = tid & 31, w = tid >> 5;
    int wm = w >> 2, wn = w & 3;
    int m0 = blockIdx.y*128, n0 = blockIdx.x*128;
    int lr = tid >> 3, lc = (tid & 7)*4;
    const float* Ap = A + (size_t)(m0+lr)*K + lc;
    const float* Bp = B + (size_t)(n0+lr)*K + lc;

    float acc[4][4][4];
    #pragma unroll
    for (int i = 0; i < 4; ++i)
        #pragma unroll
        for (int j = 0; j < 4; ++j)
            #pragma unroll
            for (int v = 0; v < 4; ++v) acc[i][j][v] = 0.f;

    int qa = lane >> 2, ra = lane & 3;

    float4 pra[4], prb[4];
    #pragma unroll
    for (int p = 0; p < 4; ++p) {
        pra[p] = *(const float4*)(Ap + (size_t)p*32*K);
        prb[p] = *(const float4*)(Bp + (size_t)p*32*K);
    }

    for (int kb = 0; kb < K; kb += 32) {
        __syncthreads();
        #pragma unroll
        for (int p = 0; p < 4; ++p) {
            unsigned* as = As + (lr + p*32)*GS + lc;
            unsigned* bs = Bs + (lr + p*32)*GS + lc;
            as[0]=f2tf32(pra[p].x); as[1]=f2tf32(pra[p].y); as[2]=f2tf32(pra[p].z); as[3]=f2tf32(pra[p].w);
            bs[0]=f2tf32(prb[p].x); bs[1]=f2tf32(prb[p].y); bs[2]=f2tf32(prb[p].z); bs[3]=f2tf32(prb[p].w);
        }
        __syncthreads();
        if (kb + 32 < K) {
            #pragma unroll
            for (int p = 0; p < 4; ++p) {
                pra[p] = *(const float4*)(Ap + (size_t)p*32*K + kb + 32);
                prb[p] = *(const float4*)(Bp + (size_t)p*32*K + kb + 32);
            }
        }
        #pragma unroll
        for (int ks = 0; ks < 4; ++ks) {
            unsigned af[4][4], bf[4][2];
            #pragma unroll
            for (int mt = 0; mt < 4; ++mt) {
                const unsigned* p = As + (wm*64 + mt*16 + qa)*GS + ks*8 + ra;
                af[mt][0] = p[0];
                af[mt][1] = p[8*GS];
                af[mt][2] = p[4];
                af[mt][3] = p[8*GS + 4];
            }
            #pragma unroll
            for (int nt = 0; nt < 4; ++nt) {
                const unsigned* p = Bs + (wn*32 + nt*8 + qa)*GS + ks*8 + ra;
                bf[nt][0] = p[0];
                bf[nt][1] = p[4];
            }
            #pragma unroll
            for (int mt = 0; mt < 4; ++mt)
                #pragma unroll
                for (int nt = 0; nt < 4; ++nt)
                    mma_tf32(acc[mt][nt], af[mt], bf[nt]);
        }
    }

    #pragma unroll
    for (int mt = 0; mt < 4; ++mt) {
        int row = m0 + wm*64 + mt*16 + qa;
        #pragma unroll
        for (int nt = 0; nt < 4; ++nt) {
            int col = n0 + wn*32 + nt*8 + ra*2;
            float2 c0 = {acc[mt][nt][0], acc[mt][nt][1]};
            float2 c1 = {acc[mt][nt][2], acc[mt][nt][3]};
            *(float2*)(C + (size_t)row*N + col) = c0;
            *(float2*)(C + (size_t)(row+8)*N + col) = c1;
        }
    }
}

// ---------------- reorg: split heads + rmsnorm(g) + g2 ----------------
__global__ __launch_bounds__(256) void reorg_kernel(const float* __restrict__ gnw) {
    int gw = (blockIdx.x*256 + threadIdx.x) >> 5;
    int lane = threadIdx.x & 31;
    if (gw >= T_N*H_N) return;
    int t = gw / H_N, h = gw % H_N;
    const float* row = g_qkvg + (size_t)t*(4*C_N);
    int col = h*D_N + lane*2;
    int o = (h*T_N + t)*D_N + lane*2;
    float2 qv = *(const float2*)(row + col);
    float2 kv = *(const float2*)(row + C_N + col);
    float2 vv = *(const float2*)(row + 2*C_N + col);
    float2 gv = *(const float2*)(row + 3*C_N + col);
    *(float2*)(g_q + o) = qv;
    *(float2*)(g_k + o) = kv;
    *(float2*)(g_v + o) = vv;
    float ss = gv.x*gv.x + gv.y*gv.y;
    #pragma unroll
    for (int m = 16; m; m >>= 1) ss += __shfl_xor_sync(0xffffffffu, ss, m);
    float r = rsqrtf(ss*(1.0f/D_N) + 1e-6f);
    float2 wv = *(const float2*)(gnw + lane*2);
    float g0 = gv.x*r*wv.x, g1 = gv.y*r*wv.y;
    float2 gn = {g0, g1};
    *(float2*)(g_g + o) = gn;
    float s2 = g0*g0 + g1*g1;
    #pragma unroll
    for (int m = 16; m; m >>= 1) s2 += __shfl_xor_sync(0xffffffffu, s2, m);
    if (lane == 0) g_g2[h*T_N + t] = s2;
}

// ---------------- split-j flash attention partial (tensor-core) ----------------
// smem word offsets
#define QS_O   0
#define GI_O   4352
#define KS_O   8704
#define GJ_O   13056
#define VS_O   17408
#define PS_O   21760
#define G2I_O  26112
#define G2J_O  26176
#define DWS_O  26240
#define REDM_O 26304
#define REDL_O 26432
#define ATT_SMEM_WORDS 26560
#define ATT_SMEM_BYTES (ATT_SMEM_WORDS*4)

__global__ __launch_bounds__(256, 2) void attn_part() {
    extern __shared__ unsigned smu[];
    float* smf = (float*)smu;
    unsigned* Qs = smu + QS_O;           // [64][68] tf32
    float*    Gis = smf + GI_O;          // [64][68] f32
    unsigned* Ks = smu + KS_O;           // [64][68] tf32
    float*    Gjs = smf + GJ_O;          // [64][68] f32
    unsigned* Vs = smu + VS_O;           // [d][j] tf32 (transposed)
    unsigned* Ps = smu + PS_O;           // [64][68] tf32
    float* g2i_s = smf + G2I_O;
    float* g2j_s = smf + G2J_O;
    float* dws   = smf + DWS_O;
    float* redm  = smf + REDM_O;         // [2][64]
    float* redl  = smf + REDL_O;         // [2][64]

    int bid = blockIdx.x;
    int h = bid % H_N;
    int u = bid / H_N;
    int it = c_uit[u], cch = c_uc[u];
    int i0 = it * 64;
    int jt0 = cch*4, jt1 = min(jt0+3, it);
    int uidx = c_off[it] + cch;
    int tid = threadIdx.x;
    int lane = tid & 31, w = tid >> 5;
    int wm = w >> 1, wn = w & 1;          // 4x2 warp grid
    int qa = lane >> 2, ra = lane & 3;
    int row0 = wm*16 + qa;                // rh=0 row; rh=1: +8

    int fast = g_c.fastf[h];
    float i4t0 = g_c.i4t0[h], fA = g_c.fA[h], fB = g_c.fB[h];
    float neghb = g_c.neghb[h], dpl = g_c.dpl[h], glk = g_c.glk[h];

    // load Q (tf32) & Gi (f32), row-major stride 68
    const float* qg  = g_q + (size_t)(h*T_N + i0)*D_N;
    const float* gig = g_g + (size_t)(h*T_N + i0)*D_N;
    #pragma unroll
    for (int p = 0; p < 4; ++p) {
        int e = tid + p*256;
        int r = e >> 4, dc = (e & 15)*4;
        float4 a = *(const float4*)(qg + r*D_N + dc);
        uint4 ua; ua.x=f2tf32(a.x); ua.y=f2tf32(a.y); ua.z=f2tf32(a.z); ua.w=f2tf32(a.w);
        *(uint4*)(Qs + r*68 + dc) = ua;
        float4 b = *(const float4*)(gig + r*D_N + dc);
        *(float4*)(Gis + r*68 + dc) = b;
    }
    if (tid < 64) g2i_s[tid] = g_g2[h*T_N + i0 + tid];

    float m_r[2] = {-1e30f, -1e30f}, l_r[2] = {0.f, 0.f};
    float apv[4][4];
    #pragma unroll
    for (int nt = 0; nt < 4; ++nt)
        #pragma unroll
        for (int c = 0; c < 4; ++c) apv[nt][c] = 0.f;

    for (int jt = jt0; jt <= jt1; ++jt) {
        int j0 = jt*64;
        __syncthreads();
        const float* kg  = g_k + (size_t)(h*T_N + j0)*D_N;
        const float* gjg = g_g + (size_t)(h*T_N + j0)*D_N;
        const float* vg  = g_v + (size_t)(h*T_N + j0)*D_N;
        #pragma unroll
        for (int p = 0; p < 4; ++p) {
            int e = tid + p*256;
            int r = e >> 4, dc = (e & 15)*4;
            float4 a = *(const float4*)(kg + r*D_N + dc);
            uint4 ua; ua.x=f2tf32(a.x); ua.y=f2tf32(a.y); ua.z=f2tf32(a.z); ua.w=f2tf32(a.w);
            *(uint4*)(Ks + r*68 + dc) = ua;
            float4 b = *(const float4*)(gjg + r*D_N + dc);
            *(float4*)(Gjs + r*68 + dc) = b;
            // V transposed [d][j]
            int j = e & 63, dg = (e >> 6)*4;
            float4 v = *(const float4*)(vg + j*D_N + dg);
            Vs[(dg+0)*68 + j] = f2tf32(v.x);
            Vs[(dg+1)*68 + j] = f2tf32(v.y);
            Vs[(dg+2)*68 + j] = f2tf32(v.z);
            Vs[(dg+3)*68 + j] = f2tf32(v.w);
        }
        if (tid < 64) g2j_s[tid] = g_g2[h*T_N + j0 + tid];
        __syncthreads();

        // ---- QK + GG (3xTF32) MMAs ----
        float dqk[4][4], dgg[4][4];
        #pragma unroll
        for (int nt = 0; nt < 4; ++nt)
            #pragma unroll
            for (int c = 0; c < 4; ++c) { dqk[nt][c] = 0.f; dgg[nt][c] = 0.f; }

        #pragma unroll
        for (int ks = 0; ks < 8; ++ks) {
            int kc = ks*8 + ra;
            const unsigned* qp = Qs + row0*68 + kc;
            unsigned af[4] = {qp[0], qp[8*68], qp[4], qp[8*68+4]};
            const float* gp = Gis + row0*68 + kc;
            float w0 = gp[0], w1 = gp[8*68], w2 = gp[4], w3 = gp[8*68+4];
            unsigned ghi[4], glo[4];
            ghi[0]=f2tf32(w0); glo[0]=f2tf32(w0-__uint_as_float(ghi[0]));
            ghi[1]=f2tf32(w1); glo[1]=f2tf32(w1-__uint_as_float(ghi[1]));
            ghi[2]=f2tf32(w2); glo[2]=f2tf32(w2-__uint_as_float(ghi[2]));
            ghi[3]=f2tf32(w3); glo[3]=f2tf32(w3-__uint_as_float(ghi[3]));
            #pragma unroll
            for (int nt = 0; nt < 4; ++nt) {
                int nb = wn*32 + nt*8 + qa;
                const unsigned* kp = Ks + nb*68 + kc;
                unsigned bf[2] = {kp[0], kp[4]};
                const float* gjp = Gjs + nb*68 + kc;
                float u0 = gjp[0], u1 = gjp[4];
                unsigned bhi[2], blo[2];
                bhi[0]=f2tf32(u0); blo[0]=f2tf32(u0-__uint_as_float(bhi[0]));
                bhi[1]=f2tf32(u1); blo[1]=f2tf32(u1-__uint_as_float(bhi[1]));
                mma_tf32(dqk[nt], af, bf);
                mma_tf32(dgg[nt], ghi, bhi);
                mma_tf32(dgg[nt], ghi, blo);
                mma_tf32(dgg[nt], glo, bhi);
            }
        }

        // ---- epilogue: blended scores ----
        int diag = (jt == it);
        float mt[2] = {-1e30f, -1e30f};
        #pragma unroll
        for (int nt = 0; nt < 4; ++nt) {
            #pragma unroll
            for (int c = 0; c < 4; ++c) {
                int rh = c >> 1, pp = c & 1;
                int rl = row0 + rh*8;
                int cl = wn*32 + nt*8 + 2*ra + pp;
                float bl = -1e30f;
                if (j0 + cl <= i0 + rl) {
                    float s = fmaxf(g2i_s[rl] + g2j_s[cl] - 2.f*dgg[nt][c], 0.f);
                    if (fast) {
                        bl = fmaf(dqk[nt][c], dpl, fmaf(fA, lg2f_(fmaf(s, i4t0, 1.f)), fB));
                    } else {
                        float Ksum = 0.f;
                        #pragma unroll
                        for (int t = 0; t < 8; ++t) {
                            float uu = fmaf(s, g_c.inv4tau[h][t], 1.f);
                            Ksum = fmaf(g_c.wte[h][t], ex2f_(neghb * lg2f_(uu)), Ksum);
                        }
                        bl = fmaf(dqk[nt][c], dpl, glk * lg2f_(Ksum));
                    }
                }
                dqk[nt][c] = bl;
                mt[rh] = fmaxf(mt[rh], bl);
            }
        }
        mt[0] = fmaxf(mt[0], __shfl_xor_sync(0xffffffffu, mt[0], 1));
        mt[0] = fmaxf(mt[0], __shfl_xor_sync(0xffffffffu, mt[0], 2));
        mt[1] = fmaxf(mt[1], __shfl_xor_sync(0xffffffffu, mt[1], 1));
        mt[1] = fmaxf(mt[1], __shfl_xor_sync(0xffffffffu, mt[1], 2));
        redm[wn*64 + row0]     = mt[0];
        redm[wn*64 + row0 + 8] = mt[1];
        __syncthreads();
        float sc[2];
        #pragma unroll
        for (int rh = 0; rh < 2; ++rh) {
            int rl = row0 + rh*8;
            float mtile = fmaxf(redm[rl], redm[64 + rl]);
            float mnew = fmaxf(m_r[rh], mtile);
            sc[rh] = ex2f_((m_r[rh] - mnew)*LOG2E);
            m_r[rh] = mnew;
        }
        #pragma unroll
        for (int nt = 0; nt < 4; ++nt) {
            apv[nt][0] *= sc[0]; apv[nt][1] *= sc[0];
            apv[nt][2] *= sc[1]; apv[nt][3] *= sc[1];
        }
        float psum[2] = {0.f, 0.f};
        #pragma unroll
        for (int nt = 0; nt < 4; ++nt) {
            int cl = wn*32 + nt*8 + 2*ra;
            float p00 = ex2f_((dqk[nt][0] - m_r[0])*LOG2E);
            float p01 = ex2f_((dqk[nt][1] - m_r[0])*LOG2E);
            float p10 = ex2f_((dqk[nt][2] - m_r[1])*LOG2E);
            float p11 = ex2f_((dqk[nt][3] - m_r[1])*LOG2E);
            psum[0] += p00 + p01;
            psum[1] += p10 + p11;
            if (diag) {
                int rl0 = row0, rl1 = row0 + 8;
                if (rl0 == cl) dws[rl0] = p00; else if (rl0 == cl+1) dws[rl0] = p01;
                if (rl1 == cl) dws[rl1] = p10; else if (rl1 == cl+1) dws[rl1] = p11;
            }
            uint2 s0; s0.x = f2tf32(p00); s0.y = f2tf32(p01);
            uint2 s1; s1.x = f2tf32(p10); s1.y = f2tf32(p11);
            *(uint2*)(Ps + row0*68 + cl) = s0;
            *(uint2*)(Ps + (row0+8)*68 + cl) = s1;
        }
        psum[0] += __shfl_xor_sync(0xffffffffu, psum[0], 1);
        psum[0] += __shfl_xor_sync(0xffffffffu, psum[0], 2);
        psum[1] += __shfl_xor_sync(0xffffffffu, psum[1], 1);
        psum[1] += __shfl_xor_sync(0xffffffffu, psum[1], 2);
        redl[wn*64 + row0]     = psum[0];
        redl[wn*64 + row0 + 8] = psum[1];
        __syncthreads();
        l_r[0] = l_r[0]*sc[0] + redl[row0]     + redl[64 + row0];
        l_r[1] = l_r[1]*sc[1] + redl[row0 + 8] + redl[64 + row0 + 8];

        // ---- PV MMAs ----
        #pragma unroll
        for (int ks = 0; ks < 8; ++ks) {
            int kc = ks*8 + ra;
            const unsigned* pp_ = Ps + row0*68 + kc;
            unsigned pf[4] = {pp_[0], pp_[8*68], pp_[4], pp_[8*68+4]};
            #pragma unroll
            for (int nt = 0; nt < 4; ++nt) {
                const unsigned* vp = Vs + (wn*32 + nt*8 + qa)*68 + kc;
                unsigned vf[2] = {vp[0], vp[4]};
                mma_tf32(apv[nt], pf, vf);
            }
        }
    }

    __syncthreads();  // dws visibility
    int base = (h*40 + uidx)*64;
    if (wn == 0 && ra == 0) {
        g_pm[base + row0]     = m_r[0];
        g_pm[base + row0 + 8] = m_r[1];
        g_pl[base + row0]     = l_r[0];
        g_pl[base + row0 + 8] = l_r[1];
    }
    #pragma unroll
    for (int nt = 0; nt < 4; ++nt) {
        int cl = wn*32 + nt*8 + 2*ra;
        float2 a0 = {apv[nt][0], apv[nt][1]};
        float2 a1 = {apv[nt][2], apv[nt][3]};
        *(float2*)(g_pacc + (size_t)(base + row0)*64 + cl) = a0;
        *(float2*)(g_pacc + (size_t)(base + row0 + 8)*64 + cl) = a1;
    }
    if (jt1 == it && tid < 64) g_dw[(h*16 + it)*64 + tid] = dws[tid];
}

// ---------------- combine partials -> g_y ----------------
__global__ __launch_bounds__(256) void attn_combine() {
    int bid = blockIdx.x;
    int h = bid % H_N, it = bid / H_N;
    int i0 = it * 64;
    int nc = it/4 + 1;
    int tid = threadIdx.x;
    int row = tid >> 2;
    int c0 = (tid & 3) * 16;
    int b0 = (h*40 + c_off[it])*64 + row;

    float mv[4], sc4[4];
    float gm = -1e30f;
    for (int c = 0; c < nc; ++c) { mv[c] = g_pm[b0 + c*64]; gm = fmaxf(gm, mv[c]); }
    float L = 0.f;
    for (int c = 0; c < nc; ++c) {
        sc4[c] = ex2f_((mv[c]-gm)*LOG2E);
        L += g_pl[b0 + c*64] * sc4[c];
    }
    float linv = 1.f / fmaxf(L, 1e-12f);
    float pii = g_dw[(h*16 + it)*64 + row] * sc4[nc-1] * linv;
    float alpha = g_c.alpha;
    float ca = 1.f - alpha;
    float cb = alpha / (1.f + pii);
    float outs = g_c.outs[h];

    for (int cc = 0; cc < 16; cc += 4) {
        float ax=0.f, ay=0.f, az=0.f, aw=0.f;
        for (int c = 0; c < nc; ++c) {
            float4 p = *(const float4*)(g_pacc + (size_t)(b0 + c*64)*64 + c0 + cc);
            float s = sc4[c];
            ax = fmaf(p.x, s, ax); ay = fmaf(p.y, s, ay);
            az = fmaf(p.z, s, az); aw = fmaf(p.w, s, aw);
        }
        float4 v = *(const float4*)(g_v + (size_t)(h*T_N + i0 + row)*D_N + c0 + cc);
        float4 o;
        float p0 = ax*linv, p1 = ay*linv, p2 = az*linv, p3 = aw*linv;
        o.x = outs * (ca*p0 + cb*(p0 + pii*v.x));
        o.y = outs * (ca*p1 + cb*(p1 + pii*v.y));
        o.z = outs * (ca*p2 + cb*(p2 + pii*v.z));
        o.w = outs * (ca*p3 + cb*(p3 + pii*v.w));
        *(float4*)(g_y + (size_t)(i0 + row)*C_N + h*D_N + c0 + cc) = o;
    }
}

// ---------------- launch ----------------
extern "C" void kernel_launch(void* const* d_in, const int* in_sizes, int n_in,
                              void* d_out, int out_size) {
    const float* x         = (const float*)d_in[0];
    const float* W_qkvg    = (const float*)d_in[1];
    const float* W_out     = (const float*)d_in[2];
    const float* lam       = (const float*)d_in[3];
    const float* log_tau   = (const float*)d_in[4];
    const float* logit_w   = (const float*)d_in[5];
    const float* beta      = (const float*)d_in[6];
    const float* out_scale = (const float*)d_in[7];
    const float* dp_scale  = (const float*)d_in[8];
    const float* logk_sc   = (const float*)d_in[9];
    const float* dt_logit  = (const float*)d_in[10];
    const float* gnw       = (const float*)d_in[11];
    float* out = (float*)d_out;

    float *qkvg_p = nullptr, *y_p = nullptr;
    cudaGetSymbolAddress((void**)&qkvg_p, g_qkvg);
    cudaGetSymbolAddress((void**)&y_p, g_y);

    cudaFuncSetAttribute(attn_part, cudaFuncAttributeMaxDynamicSharedMemorySize, ATT_SMEM_BYTES);

    const_kernel<<<1, 32>>>(lam, log_tau, logit_w, beta, out_scale, dp_scale, logk_sc, dt_logit);
    gemm_tf32<<<dim3(3072/128, 1024/128), 256>>>(x, W_qkvg, qkvg_p, T_N, 4*C_N, C_N);
    reorg_kernel<<<(T_N*H_N*32)/256, 256>>>(gnw);
    attn_part<<<480, 256, ATT_SMEM_BYTES>>>();
    attn_combine<<<192, 256>>>();
    gemm_tf32<<<dim3(768/128, 1024/128), 256>>>(y_p, W_out, out, T_N, C_N, C_N);
}

// round 5
// speedup vs baseline: 2.8617x; 1.1827x over previous
#include <cuda_runtime.h>
#include <cuda_bf16.h>

#define T_N 1024
#define C_N 768
#define H_N 12
#define D_N 64
#define NT_N 8
#define LOG2E 1.4426950408889634f

// ---------------- scratch (static device globals; no allocation) ----------------
__device__ float g_q[H_N * T_N * D_N];       // [H][T][D]
__device__ float g_k[H_N * T_N * D_N];
__device__ float g_v[H_N * T_N * D_N];
__device__ float g_g[H_N * T_N * D_N];       // raw then rmsnormed+tf32-quantized g
__device__ float g_g2[H_N * T_N];            // ||ghat||^2 per (h,t)
__device__ float g_y[T_N * C_N];             // attention out, [T][C] layout

// split-j partials: 40 units per head (chunks of <=4 j-tiles)
__device__ float g_pacc[H_N * 40 * 64 * 64]; // [h][unit][row][col]
__device__ float g_pm[H_N * 40 * 64];
__device__ float g_pl[H_N * 40 * 64];
__device__ float g_dw[H_N * 16 * 64];        // diag weights per (h,it,row)

// unit tables: heavy (4-tile) units first for scheduling
__constant__ int c_uit[40] = {15,15,15,15,14,14,14,13,13,13,12,12,12,11,11,11,10,10,9,9,8,8,7,7,6,5,4,3,
                              14,10,6,2, 13,9,5,1, 12,8,4,0};
__constant__ int c_uc[40]  = { 0, 1, 2, 3, 0, 1, 2, 0, 1, 2, 0, 1, 2, 0, 1, 2, 0, 1,0,1,0,1,0,1,0,0,0,0,
                               3, 2,1,0,  3,2,1,0,  3,2,1,0};
__constant__ int c_off[16] = {0,1,2,3,4,6,8,10,12,15,18,21,24,28,32,36};

struct Consts {
    float inv4tau[H_N][NT_N];
    float wte[H_N][NT_N];
    float neghb[H_N];
    float dpl[H_N];           // lam * dp_scale/(8*0.8)
    float glk[H_N];           // (1-lam) * logk_scale * ln2
    float outs[H_N];
    float fA[H_N], fB[H_N], i4t0[H_N];
    int   fastf[H_N];
    float alpha;
};
__device__ Consts g_c;

__device__ __forceinline__ float ex2f_(float x){ float y; asm("ex2.approx.ftz.f32 %0, %1;":"=f"(y):"f"(x)); return y; }
__device__ __forceinline__ float lg2f_(float x){ float y; asm("lg2.approx.ftz.f32 %0, %1;":"=f"(y):"f"(x)); return y; }
__device__ __forceinline__ unsigned f2tf32(float x){ unsigned y; asm("cvt.rna.tf32.f32 %0, %1;":"=r"(y):"f"(x)); return y; }

__device__ __forceinline__ void mma_tf32(float* d, const unsigned* a, const unsigned* b) {
    asm volatile(
      "mma.sync.aligned.m16n8k8.row.col.f32.tf32.tf32.f32 "
      "{%0,%1,%2,%3}, {%4,%5,%6,%7}, {%8,%9}, {%0,%1,%2,%3};\n"
      : "+f"(d[0]), "+f"(d[1]), "+f"(d[2]), "+f"(d[3])
      : "r"(a[0]), "r"(a[1]), "r"(a[2]), "r"(a[3]), "r"(b[0]), "r"(b[1]));
}

// ---------------- constants precompute ----------------
__global__ void const_kernel(const float* lam_p, const float* log_tau,
                             const float* logit_w, const float* beta,
                             const float* out_scale, const float* dp_scale,
                             const float* logk_scale, const float* dt_logit) {
    if (threadIdx.x != 0 || blockIdx.x != 0) return;
    float lam = lam_p[0];
    for (int h = 0; h < H_N; ++h) {
        float mx = -1e30f;
        for (int t = 0; t < NT_N; ++t) mx = fmaxf(mx, logit_w[h*NT_N+t]);
        float s = 0.f, e[NT_N];
        for (int t = 0; t < NT_N; ++t) { e[t] = expf(logit_w[h*NT_N+t]-mx); s += e[t]; }
        float W = 0.f;
        for (int t = 0; t < NT_N; ++t) { g_c.wte[h][t] = e[t]/s + 1e-12f; W += g_c.wte[h][t]; }
        for (int t = 0; t < NT_N; ++t) {
            float tau = fmaxf(expf(log_tau[h*NT_N+t]), 1e-6f);
            g_c.inv4tau[h][t] = 1.f/(4.f*tau);
        }
        float bc = fminf(fmaxf(beta[h], 0.5f), 2.5f);
        float neghb = -0.5f*bc;
        float dpc = dp_scale[h]/(8.0f*0.8f);
        float lks = logk_scale[h]*0.6931471805599453f;
        g_c.neghb[h] = neghb;
        g_c.dpl[h]   = lam*dpc;
        g_c.glk[h]   = (1.f-lam)*lks;
        g_c.outs[h]  = out_scale[h];
        int same = 1;
        for (int t = 1; t < NT_N; ++t) if (g_c.inv4tau[h][t] != g_c.inv4tau[h][0]) same = 0;
        g_c.fastf[h] = same;
        g_c.i4t0[h]  = g_c.inv4tau[h][0];
        g_c.fA[h]    = g_c.glk[h]*neghb;
        g_c.fB[h]    = g_c.glk[h]*log2f(W);
    }
    g_c.alpha = 0.1f/(1.f+expf(-dt_logit[0]));
}

// ---------------- tf32 GEMM 128x128, double-buffered; optional qkvg scatter ----------------
#define GS 36
#define STG128 (2*128*GS)   // words per stage (A tile + B tile)

__global__ __launch_bounds__(256, 2) void gemm_tf32_128(const float* __restrict__ A,
        const float* __restrict__ B, float* __restrict__ C, int M, int N, int K, int scatter) {
    extern __shared__ unsigned gsm[];
    int tid = threadIdx.x;
    int lane = tid & 31, w = tid >> 5;
    int wm = w >> 2, wn = w & 3;
    int m0 = blockIdx.y*128, n0 = blockIdx.x*128;
    int lr = tid >> 3, lc = (tid & 7)*4;
    const float* Ap = A + (size_t)(m0+lr)*K + lc;
    const float* Bp = B + (size_t)(n0+lr)*K + lc;

    float acc[4][4][4];
    #pragma unroll
    for (int i = 0; i < 4; ++i)
        #pragma unroll
        for (int j = 0; j < 4; ++j)
            #pragma unroll
            for (int v = 0; v < 4; ++v) acc[i][j][v] = 0.f;

    int qa = lane >> 2, ra = lane & 3;

    float4 pra[4], prb[4];
    #pragma unroll
    for (int p = 0; p < 4; ++p) {
        pra[p] = *(const float4*)(Ap + (size_t)p*32*K);
        prb[p] = *(const float4*)(Bp + (size_t)p*32*K);
    }
    {   // store stage 0
        unsigned* As = gsm;
        unsigned* Bs = gsm + 128*GS;
        #pragma unroll
        for (int p = 0; p < 4; ++p) {
            unsigned* as = As + (lr + p*32)*GS + lc;
            unsigned* bs = Bs + (lr + p*32)*GS + lc;
            as[0]=f2tf32(pra[p].x); as[1]=f2tf32(pra[p].y); as[2]=f2tf32(pra[p].z); as[3]=f2tf32(pra[p].w);
            bs[0]=f2tf32(prb[p].x); bs[1]=f2tf32(prb[p].y); bs[2]=f2tf32(prb[p].z); bs[3]=f2tf32(prb[p].w);
        }
    }
    __syncthreads();
    int cur = 0;

    for (int kb = 0; kb < K; kb += 32) {
        bool nxt = (kb + 32 < K);
        if (nxt) {
            #pragma unroll
            for (int p = 0; p < 4; ++p) {
                pra[p] = *(const float4*)(Ap + (size_t)p*32*K + kb + 32);
                prb[p] = *(const float4*)(Bp + (size_t)p*32*K + kb + 32);
            }
        }
        unsigned* As = gsm + cur*STG128;
        unsigned* Bs = As + 128*GS;
        #pragma unroll
        for (int ks = 0; ks < 4; ++ks) {
            unsigned af[4][4], bf[4][2];
            #pragma unroll
            for (int mt = 0; mt < 4; ++mt) {
                const unsigned* p = As + (wm*64 + mt*16 + qa)*GS + ks*8 + ra;
                af[mt][0] = p[0];
                af[mt][1] = p[8*GS];
                af[mt][2] = p[4];
                af[mt][3] = p[8*GS + 4];
            }
            #pragma unroll
            for (int nt = 0; nt < 4; ++nt) {
                const unsigned* p = Bs + (wn*32 + nt*8 + qa)*GS + ks*8 + ra;
                bf[nt][0] = p[0];
                bf[nt][1] = p[4];
            }
            #pragma unroll
            for (int mt = 0; mt < 4; ++mt)
                #pragma unroll
                for (int nt = 0; nt < 4; ++nt)
                    mma_tf32(acc[mt][nt], af[mt], bf[nt]);
        }
        if (nxt) {
            unsigned* As2 = gsm + (cur^1)*STG128;
            unsigned* Bs2 = As2 + 128*GS;
            #pragma unroll
            for (int p = 0; p < 4; ++p) {
                unsigned* as = As2 + (lr + p*32)*GS + lc;
                unsigned* bs = Bs2 + (lr + p*32)*GS + lc;
                as[0]=f2tf32(pra[p].x); as[1]=f2tf32(pra[p].y); as[2]=f2tf32(pra[p].z); as[3]=f2tf32(pra[p].w);
                bs[0]=f2tf32(prb[p].x); bs[1]=f2tf32(prb[p].y); bs[2]=f2tf32(prb[p].z); bs[3]=f2tf32(prb[p].w);
            }
            __syncthreads();
            cur ^= 1;
        }
    }

    #pragma unroll
    for (int mt = 0; mt < 4; ++mt) {
        int row = m0 + wm*64 + mt*16 + qa;
        #pragma unroll
        for (int nt = 0; nt < 4; ++nt) {
            float2 c0 = {acc[mt][nt][0], acc[mt][nt][1]};
            float2 c1 = {acc[mt][nt][2], acc[mt][nt][3]};
            if (scatter) {
                int colb = n0 + wn*32 + nt*8;      // section & head uniform per fragment
                int sec = colb / C_N;
                int hh = (colb % C_N) >> 6;
                int dd = (colb & 63) + ra*2;
                float* base = (sec == 0) ? g_q : (sec == 1) ? g_k : (sec == 2) ? g_v : g_g;
                *(float2*)(base + ((size_t)(hh*T_N + row)*D_N + dd)) = c0;
                *(float2*)(base + ((size_t)(hh*T_N + row + 8)*D_N + dd)) = c1;
            } else {
                int col = n0 + wn*32 + nt*8 + ra*2;
                *(float2*)(C + (size_t)row*N + col) = c0;
                *(float2*)(C + (size_t)(row+8)*N + col) = c1;
            }
        }
    }
}

// ---------------- tf32 GEMM 64x128 (for out projection) ----------------
#define STG64 ((64+128)*GS)

__global__ __launch_bounds__(256, 2) void gemm_tf32_64(const float* __restrict__ A,
        const float* __restrict__ B, float* __restrict__ C, int M, int N, int K) {
    extern __shared__ unsigned gsm[];
    int tid = threadIdx.x;
    int lane = tid & 31, w = tid >> 5;
    int wm = w >> 2, wn = w & 3;
    int m0 = blockIdx.y*64, n0 = blockIdx.x*128;
    int lr = tid >> 3, lc = (tid & 7)*4;
    const float* Ap = A + (size_t)(m0+lr)*K + lc;
    const float* Bp = B + (size_t)(n0+lr)*K + lc;

    float acc[2][4][4];
    #pragma unroll
    for (int i = 0; i < 2; ++i)
        #pragma unroll
        for (int j = 0; j < 4; ++j)
            #pragma unroll
            for (int v = 0; v < 4; ++v) acc[i][j][v] = 0.f;

    int qa = lane >> 2, ra = lane & 3;

    float4 pra[2], prb[4];
    #pragma unroll
    for (int p = 0; p < 2; ++p) pra[p] = *(const float4*)(Ap + (size_t)p*32*K);
    #pragma unroll
    for (int p = 0; p < 4; ++p) prb[p] = *(const float4*)(Bp + (size_t)p*32*K);
    {
        unsigned* As = gsm;
        unsigned* Bs = gsm + 64*GS;
        #pragma unroll
        for (int p = 0; p < 2; ++p) {
            unsigned* as = As + (lr + p*32)*GS + lc;
            as[0]=f2tf32(pra[p].x); as[1]=f2tf32(pra[p].y); as[2]=f2tf32(pra[p].z); as[3]=f2tf32(pra[p].w);
        }
        #pragma unroll
        for (int p = 0; p < 4; ++p) {
            unsigned* bs = Bs + (lr + p*32)*GS + lc;
            bs[0]=f2tf32(prb[p].x); bs[1]=f2tf32(prb[p].y); bs[2]=f2tf32(prb[p].z); bs[3]=f2tf32(prb[p].w);
        }
    }
    __syncthreads();
    int cur = 0;

    for (int kb = 0; kb < K; kb += 32) {
        bool nxt = (kb + 32 < K);
        if (nxt) {
            #pragma unroll
            for (int p = 0; p < 2; ++p) pra[p] = *(const float4*)(Ap + (size_t)p*32*K + kb + 32);
            #pragma unroll
            for (int p = 0; p < 4; ++p) prb[p] = *(const float4*)(Bp + (size_t)p*32*K + kb + 32);
        }
        unsigned* As = gsm + cur*STG64;
        unsigned* Bs = As + 64*GS;
        #pragma unroll
        for (int ks = 0; ks < 4; ++ks) {
            unsigned af[2][4], bf[4][2];
            #pragma unroll
            for (int mt = 0; mt < 2; ++mt) {
                const unsigned* p = As + (wm*32 + mt*16 + qa)*GS + ks*8 + ra;
                af[mt][0] = p[0];
                af[mt][1] = p[8*GS];
                af[mt][2] = p[4];
                af[mt][3] = p[8*GS + 4];
            }
            #pragma unroll
            for (int nt = 0; nt < 4; ++nt) {
                const unsigned* p = Bs + (wn*32 + nt*8 + qa)*GS + ks*8 + ra;
                bf[nt][0] = p[0];
                bf[nt][1] = p[4];
            }
            #pragma unroll
            for (int mt = 0; mt < 2; ++mt)
                #pragma unroll
                for (int nt = 0; nt < 4; ++nt)
                    mma_tf32(acc[mt][nt], af[mt], bf[nt]);
        }
        if (nxt) {
            unsigned* As2 = gsm + (cur^1)*STG64;
            unsigned* Bs2 = As2 + 64*GS;
            #pragma unroll
            for (int p = 0; p < 2; ++p) {
                unsigned* as = As2 + (lr + p*32)*GS + lc;
                as[0]=f2tf32(pra[p].x); as[1]=f2tf32(pra[p].y); as[2]=f2tf32(pra[p].z); as[3]=f2tf32(pra[p].w);
            }
            #pragma unroll
            for (int p = 0; p < 4; ++p) {
                unsigned* bs = Bs2 + (lr + p*32)*GS + lc;
                bs[0]=f2tf32(prb[p].x); bs[1]=f2tf32(prb[p].y); bs[2]=f2tf32(prb[p].z); bs[3]=f2tf32(prb[p].w);
            }
            __syncthreads();
            cur ^= 1;
        }
    }

    #pragma unroll
    for (int mt = 0; mt < 2; ++mt) {
        int row = m0 + wm*32 + mt*16 + qa;
        #pragma unroll
        for (int nt = 0; nt < 4; ++nt) {
            int col = n0 + wn*32 + nt*8 + ra*2;
            float2 c0 = {acc[mt][nt][0], acc[mt][nt][1]};
            float2 c1 = {acc[mt][nt][2], acc[mt][nt][3]};
            *(float2*)(C + (size_t)row*N + col) = c0;
            *(float2*)(C + (size_t)(row+8)*N + col) = c1;
        }
    }
}

// ---------------- rmsnorm g in place (quantize to tf32) + g2 ----------------
__global__ __launch_bounds__(256) void rmsnorm_g(const float* __restrict__ gnw) {
    int gw = (blockIdx.x*256 + threadIdx.x) >> 5;
    int lane = threadIdx.x & 31;
    if (gw >= H_N*T_N) return;
    float* p = g_g + (size_t)gw*D_N + lane*2;
    float2 gv = *(float2*)p;
    float ss = gv.x*gv.x + gv.y*gv.y;
    #pragma unroll
    for (int m = 16; m; m >>= 1) ss += __shfl_xor_sync(0xffffffffu, ss, m);
    float r = rsqrtf(ss*(1.0f/D_N) + 1e-6f);
    float2 wv = *(const float2*)(gnw + lane*2);
    float q0 = __uint_as_float(f2tf32(gv.x*r*wv.x));
    float q1 = __uint_as_float(f2tf32(gv.y*r*wv.y));
    float2 gq = {q0, q1};
    *(float2*)p = gq;
    float s2 = q0*q0 + q1*q1;
    #pragma unroll
    for (int m = 16; m; m >>= 1) s2 += __shfl_xor_sync(0xffffffffu, s2, m);
    if (lane == 0) g_g2[gw] = s2;
}

// ---------------- split-j flash attention partial (tensor-core) ----------------
#define QS_O   0
#define GI_O   4352
#define KS_O   8704
#define GJ_O   13056
#define VS_O   17408
#define PS_O   21760
#define G2I_O  26112
#define G2J_O  26176
#define DWS_O  26240
#define REDM_O 26304
#define REDL_O 26432
#define ATT_SMEM_WORDS 26560
#define ATT_SMEM_BYTES (ATT_SMEM_WORDS*4)

__global__ __launch_bounds__(256, 2) void attn_part() {
    extern __shared__ unsigned smu[];
    float* smf = (float*)smu;
    unsigned* Qs  = smu + QS_O;          // [64][68] tf32
    unsigned* Gis = smu + GI_O;          // [64][68] tf32 (pre-quantized g)
    unsigned* Ks  = smu + KS_O;
    unsigned* Gjs = smu + GJ_O;
    unsigned* Vs  = smu + VS_O;          // [d][j] tf32 (transposed)
    unsigned* Ps  = smu + PS_O;
    float* g2i_s = smf + G2I_O;
    float* g2j_s = smf + G2J_O;
    float* dws   = smf + DWS_O;
    float* redm  = smf + REDM_O;
    float* redl  = smf + REDL_O;

    int bid = blockIdx.x;
    int h = bid % H_N;
    int u = bid / H_N;
    int it = c_uit[u], cch = c_uc[u];
    int i0 = it * 64;
    int jt0 = cch*4, jt1 = min(jt0+3, it);
    int uidx = c_off[it] + cch;
    int tid = threadIdx.x;
    int lane = tid & 31, w = tid >> 5;
    int wm = w >> 1, wn = w & 1;
    int qa = lane >> 2, ra = lane & 3;
    int row0 = wm*16 + qa;

    int fast = g_c.fastf[h];
    float i4t0 = g_c.i4t0[h], fA = g_c.fA[h], fB = g_c.fB[h];
    float neghb = g_c.neghb[h], dpl = g_c.dpl[h], glk = g_c.glk[h];

    const float* qg  = g_q + (size_t)(h*T_N + i0)*D_N;
    const float* gig = g_g + (size_t)(h*T_N + i0)*D_N;
    #pragma unroll
    for (int p = 0; p < 4; ++p) {
        int e = tid + p*256;
        int r = e >> 4, dc = (e & 15)*4;
        float4 a = *(const float4*)(qg + r*D_N + dc);
        uint4 ua; ua.x=f2tf32(a.x); ua.y=f2tf32(a.y); ua.z=f2tf32(a.z); ua.w=f2tf32(a.w);
        *(uint4*)(Qs + r*68 + dc) = ua;
        float4 b = *(const float4*)(gig + r*D_N + dc);
        uint4 ub; ub.x=__float_as_uint(b.x); ub.y=__float_as_uint(b.y);
        ub.z=__float_as_uint(b.z); ub.w=__float_as_uint(b.w);   // already tf32-quantized
        *(uint4*)(Gis + r*68 + dc) = ub;
    }
    if (tid < 64) g2i_s[tid] = g_g2[h*T_N + i0 + tid];

    float m_r[2] = {-1e30f, -1e30f}, l_r[2] = {0.f, 0.f};
    float apv[4][4];
    #pragma unroll
    for (int nt = 0; nt < 4; ++nt)
        #pragma unroll
        for (int c = 0; c < 4; ++c) apv[nt][c] = 0.f;

    for (int jt = jt0; jt <= jt1; ++jt) {
        int j0 = jt*64;
        __syncthreads();
        const float* kg  = g_k + (size_t)(h*T_N + j0)*D_N;
        const float* gjg = g_g + (size_t)(h*T_N + j0)*D_N;
        const float* vg  = g_v + (size_t)(h*T_N + j0)*D_N;
        #pragma unroll
        for (int p = 0; p < 4; ++p) {
            int e = tid + p*256;
            int r = e >> 4, dc = (e & 15)*4;
            float4 a = *(const float4*)(kg + r*D_N + dc);
            uint4 ua; ua.x=f2tf32(a.x); ua.y=f2tf32(a.y); ua.z=f2tf32(a.z); ua.w=f2tf32(a.w);
            *(uint4*)(Ks + r*68 + dc) = ua;
            float4 b = *(const float4*)(gjg + r*D_N + dc);
            uint4 ub; ub.x=__float_as_uint(b.x); ub.y=__float_as_uint(b.y);
            ub.z=__float_as_uint(b.z); ub.w=__float_as_uint(b.w);
            *(uint4*)(Gjs + r*68 + dc) = ub;
            int j = e & 63, dg = (e >> 6)*4;
            float4 v = *(const float4*)(vg + j*D_N + dg);
            Vs[(dg+0)*68 + j] = f2tf32(v.x);
            Vs[(dg+1)*68 + j] = f2tf32(v.y);
            Vs[(dg+2)*68 + j] = f2tf32(v.z);
            Vs[(dg+3)*68 + j] = f2tf32(v.w);
        }
        if (tid < 64) g2j_s[tid] = g_g2[h*T_N + j0 + tid];
        __syncthreads();

        // ---- QK + GG MMAs (both plain tf32) ----
        float dqk[4][4], dgg[4][4];
        #pragma unroll
        for (int nt = 0; nt < 4; ++nt)
            #pragma unroll
            for (int c = 0; c < 4; ++c) { dqk[nt][c] = 0.f; dgg[nt][c] = 0.f; }

        #pragma unroll
        for (int ks = 0; ks < 8; ++ks) {
            int kc = ks*8 + ra;
            const unsigned* qp = Qs + row0*68 + kc;
            unsigned af[4] = {qp[0], qp[8*68], qp[4], qp[8*68+4]};
            const unsigned* gp = Gis + row0*68 + kc;
            unsigned gf[4] = {gp[0], gp[8*68], gp[4], gp[8*68+4]};
            #pragma unroll
            for (int nt = 0; nt < 4; ++nt) {
                int nb = wn*32 + nt*8 + qa;
                const unsigned* kp = Ks + nb*68 + kc;
                unsigned bf[2] = {kp[0], kp[4]};
                const unsigned* gjp = Gjs + nb*68 + kc;
                unsigned bgf[2] = {gjp[0], gjp[4]};
                mma_tf32(dqk[nt], af, bf);
                mma_tf32(dgg[nt], gf, bgf);
            }
        }

        // ---- epilogue: blended scores ----
        int diag = (jt == it);
        float mt[2] = {-1e30f, -1e30f};
        #pragma unroll
        for (int nt = 0; nt < 4; ++nt) {
            #pragma unroll
            for (int c = 0; c < 4; ++c) {
                int rh = c >> 1, pp = c & 1;
                int rl = row0 + rh*8;
                int cl = wn*32 + nt*8 + 2*ra + pp;
                float bl = -1e30f;
                if (j0 + cl <= i0 + rl) {
                    float s = fmaxf(g2i_s[rl] + g2j_s[cl] - 2.f*dgg[nt][c], 0.f);
                    if (fast) {
                        bl = fmaf(dqk[nt][c], dpl, fmaf(fA, lg2f_(fmaf(s, i4t0, 1.f)), fB));
                    } else {
                        float Ksum = 0.f;
                        #pragma unroll
                        for (int t = 0; t < 8; ++t) {
                            float uu = fmaf(s, g_c.inv4tau[h][t], 1.f);
                            Ksum = fmaf(g_c.wte[h][t], ex2f_(neghb * lg2f_(uu)), Ksum);
                        }
                        bl = fmaf(dqk[nt][c], dpl, glk * lg2f_(Ksum));
                    }
                }
                dqk[nt][c] = bl;
                mt[rh] = fmaxf(mt[rh], bl);
            }
        }
        mt[0] = fmaxf(mt[0], __shfl_xor_sync(0xffffffffu, mt[0], 1));
        mt[0] = fmaxf(mt[0], __shfl_xor_sync(0xffffffffu, mt[0], 2));
        mt[1] = fmaxf(mt[1], __shfl_xor_sync(0xffffffffu, mt[1], 1));
        mt[1] = fmaxf(mt[1], __shfl_xor_sync(0xffffffffu, mt[1], 2));
        redm[wn*64 + row0]     = mt[0];
        redm[wn*64 + row0 + 8] = mt[1];
        __syncthreads();
        float sc[2];
        #pragma unroll
        for (int rh = 0; rh < 2; ++rh) {
            int rl = row0 + rh*8;
            float mtile = fmaxf(redm[rl], redm[64 + rl]);
            float mnew = fmaxf(m_r[rh], mtile);
            sc[rh] = ex2f_((m_r[rh] - mnew)*LOG2E);
            m_r[rh] = mnew;
        }
        #pragma unroll
        for (int nt = 0; nt < 4; ++nt) {
            apv[nt][0] *= sc[0]; apv[nt][1] *= sc[0];
            apv[nt][2] *= sc[1]; apv[nt][3] *= sc[1];
        }
        float psum[2] = {0.f, 0.f};
        #pragma unroll
        for (int nt = 0; nt < 4; ++nt) {
            int cl = wn*32 + nt*8 + 2*ra;
            float p00 = ex2f_((dqk[nt][0] - m_r[0])*LOG2E);
            float p01 = ex2f_((dqk[nt][1] - m_r[0])*LOG2E);
            float p10 = ex2f_((dqk[nt][2] - m_r[1])*LOG2E);
            float p11 = ex2f_((dqk[nt][3] - m_r[1])*LOG2E);
            psum[0] += p00 + p01;
            psum[1] += p10 + p11;
            if (diag) {
                int rl0 = row0, rl1 = row0 + 8;
                if (rl0 == cl) dws[rl0] = p00; else if (rl0 == cl+1) dws[rl0] = p01;
                if (rl1 == cl) dws[rl1] = p10; else if (rl1 == cl+1) dws[rl1] = p11;
            }
            uint2 s0; s0.x = f2tf32(p00); s0.y = f2tf32(p01);
            uint2 s1; s1.x = f2tf32(p10); s1.y = f2tf32(p11);
            *(uint2*)(Ps + row0*68 + cl) = s0;
            *(uint2*)(Ps + (row0+8)*68 + cl) = s1;
        }
        psum[0] += __shfl_xor_sync(0xffffffffu, psum[0], 1);
        psum[0] += __shfl_xor_sync(0xffffffffu, psum[0], 2);
        psum[1] += __shfl_xor_sync(0xffffffffu, psum[1], 1);
        psum[1] += __shfl_xor_sync(0xffffffffu, psum[1], 2);
        redl[wn*64 + row0]     = psum[0];
        redl[wn*64 + row0 + 8] = psum[1];
        __syncthreads();
        l_r[0] = l_r[0]*sc[0] + redl[row0]     + redl[64 + row0];
        l_r[1] = l_r[1]*sc[1] + redl[row0 + 8] + redl[64 + row0 + 8];

        // ---- PV MMAs ----
        #pragma unroll
        for (int ks = 0; ks < 8; ++ks) {
            int kc = ks*8 + ra;
            const unsigned* pp_ = Ps + row0*68 + kc;
            unsigned pf[4] = {pp_[0], pp_[8*68], pp_[4], pp_[8*68+4]};
            #pragma unroll
            for (int nt = 0; nt < 4; ++nt) {
                const unsigned* vp = Vs + (wn*32 + nt*8 + qa)*68 + kc;
                unsigned vf[2] = {vp[0], vp[4]};
                mma_tf32(apv[nt], pf, vf);
            }
        }
    }

    __syncthreads();
    int base = (h*40 + uidx)*64;
    if (wn == 0 && ra == 0) {
        g_pm[base + row0]     = m_r[0];
        g_pm[base + row0 + 8] = m_r[1];
        g_pl[base + row0]     = l_r[0];
        g_pl[base + row0 + 8] = l_r[1];
    }
    #pragma unroll
    for (int nt = 0; nt < 4; ++nt) {
        int cl = wn*32 + nt*8 + 2*ra;
        float2 a0 = {apv[nt][0], apv[nt][1]};
        float2 a1 = {apv[nt][2], apv[nt][3]};
        *(float2*)(g_pacc + (size_t)(base + row0)*64 + cl) = a0;
        *(float2*)(g_pacc + (size_t)(base + row0 + 8)*64 + cl) = a1;
    }
    if (jt1 == it && tid < 64) g_dw[(h*16 + it)*64 + tid] = dws[tid];
}

// ---------------- combine partials -> g_y ----------------
__global__ __launch_bounds__(256) void attn_combine() {
    int bid = blockIdx.x;
    int h = bid % H_N, it = bid / H_N;
    int i0 = it * 64;
    int nc = it/4 + 1;
    int tid = threadIdx.x;
    int row = tid >> 2;
    int c0 = (tid & 3) * 16;
    int b0 = (h*40 + c_off[it])*64 + row;

    float mv[4], sc4[4];
    float gm = -1e30f;
    for (int c = 0; c < nc; ++c) { mv[c] = g_pm[b0 + c*64]; gm = fmaxf(gm, mv[c]); }
    float L = 0.f;
    for (int c = 0; c < nc; ++c) {
        sc4[c] = ex2f_((mv[c]-gm)*LOG2E);
        L += g_pl[b0 + c*64] * sc4[c];
    }
    float linv = 1.f / fmaxf(L, 1e-12f);
    float pii = g_dw[(h*16 + it)*64 + row] * sc4[nc-1] * linv;
    float alpha = g_c.alpha;
    float ca = 1.f - alpha;
    float cb = alpha / (1.f + pii);
    float outs = g_c.outs[h];

    for (int cc = 0; cc < 16; cc += 4) {
        float ax=0.f, ay=0.f, az=0.f, aw=0.f;
        for (int c = 0; c < nc; ++c) {
            float4 p = *(const float4*)(g_pacc + (size_t)(b0 + c*64)*64 + c0 + cc);
            float s = sc4[c];
            ax = fmaf(p.x, s, ax); ay = fmaf(p.y, s, ay);
            az = fmaf(p.z, s, az); aw = fmaf(p.w, s, aw);
        }
        float4 v = *(const float4*)(g_v + (size_t)(h*T_N + i0 + row)*D_N + c0 + cc);
        float4 o;
        float p0 = ax*linv, p1 = ay*linv, p2 = az*linv, p3 = aw*linv;
        o.x = outs * (ca*p0 + cb*(p0 + pii*v.x));
        o.y = outs * (ca*p1 + cb*(p1 + pii*v.y));
        o.z = outs * (ca*p2 + cb*(p2 + pii*v.z));
        o.w = outs * (ca*p3 + cb*(p3 + pii*v.w));
        *(float4*)(g_y + (size_t)(i0 + row)*C_N + h*D_N + c0 + cc) = o;
    }
}

// ---------------- launch ----------------
extern "C" void kernel_launch(void* const* d_in, const int* in_sizes, int n_in,
                              void* d_out, int out_size) {
    const float* x         = (const float*)d_in[0];
    const float* W_qkvg    = (const float*)d_in[1];
    const float* W_out     = (const float*)d_in[2];
    const float* lam       = (const float*)d_in[3];
    const float* log_tau   = (const float*)d_in[4];
    const float* logit_w   = (const float*)d_in[5];
    const float* beta      = (const float*)d_in[6];
    const float* out_scale = (const float*)d_in[7];
    const float* dp_scale  = (const float*)d_in[8];
    const float* logk_sc   = (const float*)d_in[9];
    const float* dt_logit  = (const float*)d_in[10];
    const float* gnw       = (const float*)d_in[11];
    float* out = (float*)d_out;

    float* y_p = nullptr;
    cudaGetSymbolAddress((void**)&y_p, g_y);

    const int G128_SMEM = 2*STG128*4;
    const int G64_SMEM  = 2*STG64*4;
    cudaFuncSetAttribute(gemm_tf32_128, cudaFuncAttributeMaxDynamicSharedMemorySize, G128_SMEM);
    cudaFuncSetAttribute(gemm_tf32_64,  cudaFuncAttributeMaxDynamicSharedMemorySize, G64_SMEM);
    cudaFuncSetAttribute(attn_part, cudaFuncAttributeMaxDynamicSharedMemorySize, ATT_SMEM_BYTES);

    const_kernel<<<1, 32>>>(lam, log_tau, logit_w, beta, out_scale, dp_scale, logk_sc, dt_logit);
    gemm_tf32_128<<<dim3(3072/128, 1024/128), 256, G128_SMEM>>>(x, W_qkvg, nullptr, T_N, 4*C_N, C_N, 1);
    rmsnorm_g<<<(H_N*T_N*32)/256, 256>>>(gnw);
    attn_part<<<480, 256, ATT_SMEM_BYTES>>>();
    attn_combine<<<192, 256>>>();
    gemm_tf32_64<<<dim3(768/128, 1024/64), 256, G64_SMEM>>>(y_p, W_out, out, T_N, C_N, C_N);
}